// round 9
// baseline (speedup 1.0000x reference)
#include <cuda_runtime.h>
#include <cuda_bf16.h>
#include <math.h>

// Problem constants
#define B_ 2
#define T_ 4096
#define C_ 2048
#define H_ 16
#define D_ 128
#define W_ 1024
#define M_ (B_*T_)          // 8192 rows
#define SCALE_ (0.08838834764831845f)   // 1/sqrt(128)

// ---------------- scratch (device globals; no cudaMalloc allowed) ----------
__device__ float g_q[(size_t)M_ * C_];
__device__ float g_k[(size_t)M_ * C_];
__device__ float g_v[(size_t)M_ * C_];
__device__ float g_o[(size_t)M_ * C_];
__device__ float g_xt[(size_t)M_ * C_];       // tf32-rounded x
__device__ float g_wq[(size_t)C_ * C_];
__device__ float g_wk[(size_t)C_ * C_];
__device__ float g_wv[(size_t)C_ * C_];
__device__ float g_wp[(size_t)C_ * C_];

// ---------------- common helpers -------------------------------------------
__device__ __forceinline__ unsigned f2tf(float f) {
    unsigned u;
    asm("cvt.rna.tf32.f32 %0, %1;" : "=r"(u) : "f"(f));
    return u;
}

__device__ __forceinline__ void mma_tf32(float* c, const unsigned* a, const unsigned* b) {
    asm volatile(
        "mma.sync.aligned.m16n8k8.row.col.f32.tf32.tf32.f32 "
        "{%0,%1,%2,%3}, {%4,%5,%6,%7}, {%8,%9}, {%0,%1,%2,%3};"
        : "+f"(c[0]), "+f"(c[1]), "+f"(c[2]), "+f"(c[3])
        : "r"(a[0]), "r"(a[1]), "r"(a[2]), "r"(a[3]), "r"(b[0]), "r"(b[1]));
}

__device__ __forceinline__ void cp16(unsigned s_addr, const float* g) {
    asm volatile("cp.async.cg.shared.global [%0], [%1], 16;\n" :: "r"(s_addr), "l"(g));
}

// ---------------- tf32 rounding pre-pass -----------------------------------
__global__ __launch_bounds__(256) void round_tf32_kernel(
    const float* __restrict__ in, float* __restrict__ out, int n4)
{
    int i = blockIdx.x * blockDim.x + threadIdx.x;
    if (i < n4) {
        float4 v = ((const float4*)in)[i];
        v.x = __uint_as_float(f2tf(v.x));
        v.y = __uint_as_float(f2tf(v.y));
        v.z = __uint_as_float(f2tf(v.z));
        v.w = __uint_as_float(f2tf(v.w));
        ((float4*)out)[i] = v;
    }
}

// ---------------- TF32 GEMM with cp.async 4-stage pipeline -----------------
// C = A[MxK] * B[KxN]; A,B pre-rounded to tf32 values in fp32 storage.
// 128 threads / 4 warps, warp grid 2x2, each warp computes 64x64
// (4x8 m16n8k8 tiles) -> 32 LDS per 32 MMA per k-step (was 24 per 16).
// Pipeline: 4 stages, prefetch depth 2; issue(kt+2) writes stage (kt+2)%4
// whose last consumer was compute(kt-2), protected by the per-iteration
// __syncthreads().
#define GBM 128
#define GBN 128
#define GBK 32
#define AS_STRIDE 36     // 128x36 floats
#define BS_STRIDE 136    // 32x136 floats
#define STAGE_FLOATS (GBM * AS_STRIDE + GBK * BS_STRIDE)   // 4608+4352 = 8960
#define GEMM_STAGES 4
#define GEMM_SMEM_BYTES (GEMM_STAGES * STAGE_FLOATS * 4)   // 143360
#define GEMM_THREADS 128

__global__ __launch_bounds__(GEMM_THREADS) void tf32_gemm_pipe(
    const float* __restrict__ A, const float* __restrict__ Bm,
    float* __restrict__ Cm, int M, int N, int K)
{
    extern __shared__ float sm[];
    const int tid = threadIdx.x;
    const int bx = blockIdx.x;
    const int by = blockIdx.y;
    const int lane = tid & 31;
    const int wid = tid >> 5;            // 0..3
    const int wm = (wid & 1) * 64;       // warp row offset
    const int wn = (wid >> 1) * 64;      // warp col offset
    const int g = lane >> 2;
    const int tq = lane & 3;

    const float* Abase = A + (size_t)by * GBM * K;
    const float* Bbase = Bm + bx * GBN;
    const unsigned sm_sa = (unsigned)__cvta_generic_to_shared(sm);

    float acc[4][8][4];
#pragma unroll
    for (int mt = 0; mt < 4; mt++)
#pragma unroll
        for (int nt = 0; nt < 8; nt++)
#pragma unroll
            for (int i = 0; i < 4; i++) acc[mt][nt][i] = 0.f;

    const int ntiles = K / GBK;

    auto issue = [&](int kt, int st) {
        const unsigned as0 = sm_sa + (unsigned)(st * STAGE_FLOATS) * 4u;
        const unsigned bs0 = as0 + GBM * AS_STRIDE * 4u;
#pragma unroll
        for (int i = 0; i < 8; i++) {
            const int cid = tid + i * GEMM_THREADS;   // 0..1023
            const int r = cid >> 3;                   // 0..127
            const int c = (cid & 7) * 4;              // 0..28
            cp16(as0 + (unsigned)(r * AS_STRIDE + c) * 4u,
                 Abase + (size_t)r * K + kt * GBK + c);
        }
#pragma unroll
        for (int i = 0; i < 8; i++) {
            const int cid = tid + i * GEMM_THREADS;
            const int r = cid >> 5;                   // 0..31
            const int c = (cid & 31) * 4;             // 0..124
            cp16(bs0 + (unsigned)(r * BS_STRIDE + c) * 4u,
                 Bbase + (size_t)(kt * GBK + r) * N + c);
        }
        asm volatile("cp.async.commit_group;\n");
    };

    issue(0, 0);
    issue(1, 1);

    for (int kt = 0; kt < ntiles; kt++) {
        if (kt + 2 < ntiles) issue(kt + 2, (kt + 2) % GEMM_STAGES);
        else asm volatile("cp.async.commit_group;\n");
        asm volatile("cp.async.wait_group 2;\n");
        __syncthreads();

        const float* As = sm + (kt % GEMM_STAGES) * STAGE_FLOATS;
        const float* Bs = As + GBM * AS_STRIDE;

#pragma unroll
        for (int ks = 0; ks < 4; ks++) {
            const int k = ks * 8 + tq;
            unsigned a[4][4], b[8][2];
#pragma unroll
            for (int mt = 0; mt < 4; mt++) {
                const int m = wm + mt * 16 + g;
                a[mt][0] = __float_as_uint(As[m * AS_STRIDE + k]);
                a[mt][1] = __float_as_uint(As[(m + 8) * AS_STRIDE + k]);
                a[mt][2] = __float_as_uint(As[m * AS_STRIDE + k + 4]);
                a[mt][3] = __float_as_uint(As[(m + 8) * AS_STRIDE + k + 4]);
            }
#pragma unroll
            for (int nt = 0; nt < 8; nt++) {
                const int n = wn + nt * 8 + g;
                b[nt][0] = __float_as_uint(Bs[k * BS_STRIDE + n]);
                b[nt][1] = __float_as_uint(Bs[(k + 4) * BS_STRIDE + n]);
            }
#pragma unroll
            for (int mt = 0; mt < 4; mt++)
#pragma unroll
                for (int nt = 0; nt < 8; nt++)
                    mma_tf32(acc[mt][nt], a[mt], b[nt]);
        }
    }

#pragma unroll
    for (int mt = 0; mt < 4; mt++) {
        const int r0 = by * GBM + wm + mt * 16 + g;
#pragma unroll
        for (int nt = 0; nt < 8; nt++) {
            const int c0 = bx * GBN + wn + nt * 8 + 2 * tq;
            *(float2*)(Cm + (size_t)r0 * N + c0) = make_float2(acc[mt][nt][0], acc[mt][nt][1]);
            *(float2*)(Cm + (size_t)(r0 + 8) * N + c0) = make_float2(acc[mt][nt][2], acc[mt][nt][3]);
        }
    }
}

// ---------------- gate: v += 2*sigmoid(x[:, :32] @ Wg)[h] * ve -------------
__global__ __launch_bounds__(256) void gate_kernel(
    const float* __restrict__ x, const float* __restrict__ ve,
    const float* __restrict__ Wg, float* __restrict__ v)
{
    const int m = blockIdx.x;
    const int tid = threadIdx.x;
    __shared__ float xg[32];
    __shared__ float g[H_];

    if (tid < 32) xg[tid] = x[(size_t)m * C_ + tid];
    __syncthreads();
    if (tid < H_) {
        float s = 0.f;
#pragma unroll
        for (int i = 0; i < 32; i++) s += xg[i] * Wg[i * H_ + tid];
        g[tid] = 2.f / (1.f + __expf(-s));
    }
    __syncthreads();

    const size_t base = (size_t)m * C_;
    for (int c = tid; c < C_; c += 256) {
        v[base + c] += g[c >> 7] * ve[base + c];
    }
}

// ---------------- RoPE + RMSNorm for q and k (warp per row,head) -----------
__global__ __launch_bounds__(256) void rope_rms_kernel(
    const float* __restrict__ cosT, const float* __restrict__ sinT,
    float* __restrict__ q, float* __restrict__ k)
{
    const int gw = (blockIdx.x * blockDim.x + threadIdx.x) >> 5;
    const int lane = threadIdx.x & 31;
    const int m = gw / H_;
    const int h = gw % H_;
    const int t = m % T_;

    const float c0 = cosT[t * 64 + lane];
    const float c1 = cosT[t * 64 + lane + 32];
    const float s0 = sinT[t * 64 + lane];
    const float s1 = sinT[t * 64 + lane + 32];

#pragma unroll
    for (int a = 0; a < 2; a++) {
        float* ptr = (a == 0 ? q : k) + (size_t)m * C_ + h * D_;
        float f0 = ptr[lane];
        float f1 = ptr[lane + 32];
        float f2 = ptr[lane + 64];
        float f3 = ptr[lane + 96];
        float r0 =  f0 * c0 + f2 * s0;
        float r2 = -f0 * s0 + f2 * c0;
        float r1 =  f1 * c1 + f3 * s1;
        float r3 = -f1 * s1 + f3 * c1;
        float ss = r0*r0 + r1*r1 + r2*r2 + r3*r3;
#pragma unroll
        for (int off = 16; off; off >>= 1) ss += __shfl_xor_sync(0xffffffffu, ss, off);
        float sc = rsqrtf(ss * (1.f / 128.f) + 1e-6f);
        ptr[lane]      = r0 * sc;
        ptr[lane + 32] = r1 * sc;
        ptr[lane + 64] = r2 * sc;
        ptr[lane + 96] = r3 * sc;
    }
}

// ---------------- tensor-core sliding-window attention ---------------------
#define AQ 128
#define ATK 64
#define KS_STRIDE 132
#define VS_STRIDE 136
#define PS_STRIDE 68
#define SMEM_KS_OFF 0
#define SMEM_VS_OFF (ATK * KS_STRIDE)
#define SMEM_PS_OFF (SMEM_VS_OFF + ATK * VS_STRIDE)
#define SMEM_ATTN_FLOATS (SMEM_PS_OFF + AQ * PS_STRIDE)
#define SMEM_ATTN_BYTES (SMEM_ATTN_FLOATS * 4)

__global__ __launch_bounds__(256) void attn_mma_kernel(
    const float* __restrict__ Q, const float* __restrict__ K,
    const float* __restrict__ V, float* __restrict__ O)
{
    extern __shared__ float sm[];
    float* Ks = sm + SMEM_KS_OFF;
    float* Vs = sm + SMEM_VS_OFF;
    float* Ps = sm + SMEM_PS_OFF;

    const int b = blockIdx.z;
    const int h = blockIdx.y;
    const int t0 = blockIdx.x * AQ;
    const int tid = threadIdx.x;
    const int lane = tid & 31;
    const int wid = tid >> 5;
    const int g = lane >> 2;
    const int tq = lane & 3;
    const int wm = wid * 16;

    unsigned qf[16][4];
    {
        const float* qb = Q + ((size_t)(b * T_ + t0 + wm)) * C_ + h * D_;
#pragma unroll
        for (int ks = 0; ks < 16; ks++) {
            const int c0 = ks * 8 + tq;
            qf[ks][0] = f2tf(qb[(size_t)g * C_ + c0] * SCALE_);
            qf[ks][1] = f2tf(qb[(size_t)(g + 8) * C_ + c0] * SCALE_);
            qf[ks][2] = f2tf(qb[(size_t)g * C_ + c0 + 4] * SCALE_);
            qf[ks][3] = f2tf(qb[(size_t)(g + 8) * C_ + c0 + 4] * SCALE_);
        }
    }

    float o[16][4];
#pragma unroll
    for (int nt = 0; nt < 16; nt++)
#pragma unroll
        for (int i = 0; i < 4; i++) o[nt][i] = 0.f;

    float m0 = -1e30f, m1 = -1e30f, l0 = 0.f, l1 = 0.f;
    const int trow0 = t0 + wm + g;
    const int trow1 = trow0 + 8;

    int lo = t0 - W_;
    if (lo < 0) lo = 0;

    for (int ks0 = lo; ks0 < t0 + AQ; ks0 += ATK) {
#pragma unroll
        for (int it = 0; it < 8; it++) {
            const int idx = tid + it * 256;
            const int row = idx >> 5;
            const int c4 = (idx & 31) * 4;
            const size_t gbase = ((size_t)(b * T_ + ks0 + row)) * C_ + h * D_ + c4;
            float4 kv = *(const float4*)(K + gbase);
            float4 vv = *(const float4*)(V + gbase);
            float* kd = Ks + row * KS_STRIDE + c4;
            kd[0] = __uint_as_float(f2tf(kv.x));
            kd[1] = __uint_as_float(f2tf(kv.y));
            kd[2] = __uint_as_float(f2tf(kv.z));
            kd[3] = __uint_as_float(f2tf(kv.w));
            float* vd = Vs + row * VS_STRIDE + c4;
            vd[0] = __uint_as_float(f2tf(vv.x));
            vd[1] = __uint_as_float(f2tf(vv.y));
            vd[2] = __uint_as_float(f2tf(vv.z));
            vd[3] = __uint_as_float(f2tf(vv.w));
        }
        __syncthreads();

        float s[8][4];
#pragma unroll
        for (int nt = 0; nt < 8; nt++)
#pragma unroll
            for (int i = 0; i < 4; i++) s[nt][i] = 0.f;

#pragma unroll
        for (int ksp = 0; ksp < 16; ksp++) {
            const int k = ksp * 8 + tq;
            unsigned bfr[8][2];
#pragma unroll
            for (int nt = 0; nt < 8; nt++) {
                const int n = nt * 8 + g;
                bfr[nt][0] = __float_as_uint(Ks[n * KS_STRIDE + k]);
                bfr[nt][1] = __float_as_uint(Ks[n * KS_STRIDE + k + 4]);
            }
#pragma unroll
            for (int nt = 0; nt < 8; nt++)
                mma_tf32(s[nt], qf[ksp], bfr[nt]);
        }

        float mt0 = -1e30f, mt1 = -1e30f;
#pragma unroll
        for (int nt = 0; nt < 8; nt++) {
            const int kt0 = ks0 + nt * 8 + 2 * tq;
            const int kt1 = kt0 + 1;
            s[nt][0] = (kt0 <= trow0 && kt0 >= trow0 - W_) ? s[nt][0] : -1e30f;
            s[nt][1] = (kt1 <= trow0 && kt1 >= trow0 - W_) ? s[nt][1] : -1e30f;
            s[nt][2] = (kt0 <= trow1 && kt0 >= trow1 - W_) ? s[nt][2] : -1e30f;
            s[nt][3] = (kt1 <= trow1 && kt1 >= trow1 - W_) ? s[nt][3] : -1e30f;
            mt0 = fmaxf(mt0, fmaxf(s[nt][0], s[nt][1]));
            mt1 = fmaxf(mt1, fmaxf(s[nt][2], s[nt][3]));
        }
        mt0 = fmaxf(mt0, __shfl_xor_sync(0xffffffffu, mt0, 1));
        mt0 = fmaxf(mt0, __shfl_xor_sync(0xffffffffu, mt0, 2));
        mt1 = fmaxf(mt1, __shfl_xor_sync(0xffffffffu, mt1, 1));
        mt1 = fmaxf(mt1, __shfl_xor_sync(0xffffffffu, mt1, 2));

        const float mn0 = fmaxf(m0, mt0);
        const float mn1 = fmaxf(m1, mt1);
        const float corr0 = __expf(m0 - mn0);
        const float corr1 = __expf(m1 - mn1);
        m0 = mn0; m1 = mn1;

        float ls0 = 0.f, ls1 = 0.f;
        float* pw0 = Ps + (wm + g) * PS_STRIDE;
        float* pw1 = Ps + (wm + g + 8) * PS_STRIDE;
#pragma unroll
        for (int nt = 0; nt < 8; nt++) {
            const int c = nt * 8 + 2 * tq;
            float p00 = (s[nt][0] > -1e29f) ? __expf(s[nt][0] - mn0) : 0.f;
            float p01 = (s[nt][1] > -1e29f) ? __expf(s[nt][1] - mn0) : 0.f;
            float p10 = (s[nt][2] > -1e29f) ? __expf(s[nt][2] - mn1) : 0.f;
            float p11 = (s[nt][3] > -1e29f) ? __expf(s[nt][3] - mn1) : 0.f;
            ls0 += p00 + p01;
            ls1 += p10 + p11;
            pw0[c]     = __uint_as_float(f2tf(p00));
            pw0[c + 1] = __uint_as_float(f2tf(p01));
            pw1[c]     = __uint_as_float(f2tf(p10));
            pw1[c + 1] = __uint_as_float(f2tf(p11));
        }
        ls0 += __shfl_xor_sync(0xffffffffu, ls0, 1);
        ls0 += __shfl_xor_sync(0xffffffffu, ls0, 2);
        ls1 += __shfl_xor_sync(0xffffffffu, ls1, 1);
        ls1 += __shfl_xor_sync(0xffffffffu, ls1, 2);
        l0 = l0 * corr0 + ls0;
        l1 = l1 * corr1 + ls1;

#pragma unroll
        for (int nt = 0; nt < 16; nt++) {
            o[nt][0] *= corr0; o[nt][1] *= corr0;
            o[nt][2] *= corr1; o[nt][3] *= corr1;
        }

        __syncwarp();

#pragma unroll
        for (int ksp = 0; ksp < 8; ksp++) {
            const int k = ksp * 8 + tq;
            unsigned a[4];
            a[0] = __float_as_uint(Ps[(wm + g) * PS_STRIDE + k]);
            a[1] = __float_as_uint(Ps[(wm + g + 8) * PS_STRIDE + k]);
            a[2] = __float_as_uint(Ps[(wm + g) * PS_STRIDE + k + 4]);
            a[3] = __float_as_uint(Ps[(wm + g + 8) * PS_STRIDE + k + 4]);
            unsigned bfr[2];
#pragma unroll
            for (int nt = 0; nt < 16; nt++) {
                const int n = nt * 8 + g;
                bfr[0] = __float_as_uint(Vs[k * VS_STRIDE + n]);
                bfr[1] = __float_as_uint(Vs[(k + 4) * VS_STRIDE + n]);
                mma_tf32(o[nt], a, bfr);
            }
        }
        __syncthreads();
    }

    // epilogue: write tf32-rounded output (proj GEMM reads it raw)
    const float inv0 = 1.f / l0;
    const float inv1 = 1.f / l1;
    float* ob0 = O + ((size_t)(b * T_ + trow0)) * C_ + h * D_;
    float* ob1 = O + ((size_t)(b * T_ + trow1)) * C_ + h * D_;
#pragma unroll
    for (int nt = 0; nt < 16; nt++) {
        const int c = nt * 8 + 2 * tq;
        *(float2*)(ob0 + c) = make_float2(__uint_as_float(f2tf(o[nt][0] * inv0)),
                                          __uint_as_float(f2tf(o[nt][1] * inv0)));
        *(float2*)(ob1 + c) = make_float2(__uint_as_float(f2tf(o[nt][2] * inv1)),
                                          __uint_as_float(f2tf(o[nt][3] * inv1)));
    }
}

// ---------------- launch ---------------------------------------------------
extern "C" void kernel_launch(void* const* d_in, const int* in_sizes, int n_in,
                              void* d_out, int out_size)
{
    const float* x     = (const float*)d_in[0];
    const float* ve    = (const float*)d_in[1];
    const float* cosT  = (const float*)d_in[2];
    const float* sinT  = (const float*)d_in[3];
    const float* Wq    = (const float*)d_in[4];
    const float* Wk    = (const float*)d_in[5];
    const float* Wv    = (const float*)d_in[6];
    const float* Wproj = (const float*)d_in[7];
    const float* Wg    = (const float*)d_in[8];
    float* out = (float*)d_out;

    float *q, *k, *v, *o, *xt, *wq, *wk, *wv, *wp;
    cudaGetSymbolAddress((void**)&q, g_q);
    cudaGetSymbolAddress((void**)&k, g_k);
    cudaGetSymbolAddress((void**)&v, g_v);
    cudaGetSymbolAddress((void**)&o, g_o);
    cudaGetSymbolAddress((void**)&xt, g_xt);
    cudaGetSymbolAddress((void**)&wq, g_wq);
    cudaGetSymbolAddress((void**)&wk, g_wk);
    cudaGetSymbolAddress((void**)&wv, g_wv);
    cudaGetSymbolAddress((void**)&wp, g_wp);

    static int attr_set = 0;
    if (!attr_set) {
        cudaFuncSetAttribute(attn_mma_kernel,
                             cudaFuncAttributeMaxDynamicSharedMemorySize,
                             SMEM_ATTN_BYTES);
        cudaFuncSetAttribute(tf32_gemm_pipe,
                             cudaFuncAttributeMaxDynamicSharedMemorySize,
                             GEMM_SMEM_BYTES);
        attr_set = 1;
    }

    // tf32 pre-round: x and weights
    const int nx4 = (M_ * C_) / 4;
    const int nw4 = (C_ * C_) / 4;
    round_tf32_kernel<<<nx4 / 256, 256>>>(x, xt, nx4);
    round_tf32_kernel<<<nw4 / 256, 256>>>(Wq, wq, nw4);
    round_tf32_kernel<<<nw4 / 256, 256>>>(Wk, wk, nw4);
    round_tf32_kernel<<<nw4 / 256, 256>>>(Wv, wv, nw4);
    round_tf32_kernel<<<nw4 / 256, 256>>>(Wproj, wp, nw4);

    dim3 gemm_grid(C_ / GBN, M_ / GBM);
    tf32_gemm_pipe<<<gemm_grid, GEMM_THREADS, GEMM_SMEM_BYTES>>>(xt, wq, q, M_, C_, C_);
    tf32_gemm_pipe<<<gemm_grid, GEMM_THREADS, GEMM_SMEM_BYTES>>>(xt, wk, k, M_, C_, C_);
    tf32_gemm_pipe<<<gemm_grid, GEMM_THREADS, GEMM_SMEM_BYTES>>>(xt, wv, v, M_, C_, C_);

    gate_kernel<<<M_, 256>>>(x, ve, Wg, v);
    rope_rms_kernel<<<(M_ * H_) / 8, 256>>>(cosT, sinT, q, k);

    dim3 attn_grid(T_ / AQ, H_, B_);
    attn_mma_kernel<<<attn_grid, 256, SMEM_ATTN_BYTES>>>(q, k, v, o);

    tf32_gemm_pipe<<<gemm_grid, GEMM_THREADS, GEMM_SMEM_BYTES>>>(o, wp, out, M_, C_, C_);
}

// round 10
// speedup vs baseline: 1.0510x; 1.0510x over previous
#include <cuda_runtime.h>
#include <cuda_bf16.h>
#include <math.h>

// Problem constants
#define B_ 2
#define T_ 4096
#define C_ 2048
#define H_ 16
#define D_ 128
#define W_ 1024
#define M_ (B_*T_)          // 8192 rows
#define SCALE_ (0.08838834764831845f)   // 1/sqrt(128)

// ---------------- scratch (device globals; no cudaMalloc allowed) ----------
__device__ float g_q[(size_t)M_ * C_];
__device__ float g_k[(size_t)M_ * C_];
__device__ float g_v[(size_t)M_ * C_];
__device__ float g_o[(size_t)M_ * C_];
__device__ float g_xt[(size_t)M_ * C_];       // tf32-rounded x
__device__ float g_wq[(size_t)C_ * C_];
__device__ float g_wk[(size_t)C_ * C_];
__device__ float g_wv[(size_t)C_ * C_];
__device__ float g_wp[(size_t)C_ * C_];

// ---------------- common helpers -------------------------------------------
__device__ __forceinline__ unsigned f2tf(float f) {
    unsigned u;
    asm("cvt.rna.tf32.f32 %0, %1;" : "=r"(u) : "f"(f));
    return u;
}

__device__ __forceinline__ void mma_tf32(float* c, const unsigned* a, const unsigned* b) {
    asm volatile(
        "mma.sync.aligned.m16n8k8.row.col.f32.tf32.tf32.f32 "
        "{%0,%1,%2,%3}, {%4,%5,%6,%7}, {%8,%9}, {%0,%1,%2,%3};"
        : "+f"(c[0]), "+f"(c[1]), "+f"(c[2]), "+f"(c[3])
        : "r"(a[0]), "r"(a[1]), "r"(a[2]), "r"(a[3]), "r"(b[0]), "r"(b[1]));
}

__device__ __forceinline__ void cp16(unsigned s_addr, const float* g) {
    asm volatile("cp.async.cg.shared.global [%0], [%1], 16;\n" :: "r"(s_addr), "l"(g));
}

// ---------------- tf32 rounding pre-pass -----------------------------------
__global__ __launch_bounds__(256) void round_tf32_kernel(
    const float* __restrict__ in, float* __restrict__ out, int n4)
{
    int i = blockIdx.x * blockDim.x + threadIdx.x;
    if (i < n4) {
        float4 v = ((const float4*)in)[i];
        v.x = __uint_as_float(f2tf(v.x));
        v.y = __uint_as_float(f2tf(v.y));
        v.z = __uint_as_float(f2tf(v.z));
        v.w = __uint_as_float(f2tf(v.w));
        ((float4*)out)[i] = v;
    }
}

// ---------------- TF32 GEMM with cp.async 4-stage pipeline -----------------
// C = A[MxK] * B[KxN]; A,B pre-rounded to tf32 values in fp32 storage.
// CTA tile 256x128, 256 threads / 8 warps in 4x2 grid, each warp 64x64
// (4x8 m16n8k8 tiles): LDS/MMA = 1.0 AND 2 warps/SMSP (round-9 lesson:
// 1 warp/SMSP starves the issue stage).
// Pipeline: 4 stages, prefetch depth 2; issue(kt+2) writes stage (kt+2)%4
// whose last consumer was compute(kt-2), protected by the per-iteration
// __syncthreads().
#define GBM 256
#define GBN 128
#define GBK 32
#define AS_STRIDE 36     // 256x36 floats
#define BS_STRIDE 136    // 32x136 floats
#define STAGE_FLOATS (GBM * AS_STRIDE + GBK * BS_STRIDE)   // 9216+4352 = 13568
#define GEMM_STAGES 4
#define GEMM_SMEM_BYTES (GEMM_STAGES * STAGE_FLOATS * 4)   // 217088
#define GEMM_THREADS 256

__global__ __launch_bounds__(GEMM_THREADS) void tf32_gemm_pipe(
    const float* __restrict__ A, const float* __restrict__ Bm,
    float* __restrict__ Cm, int M, int N, int K)
{
    extern __shared__ float sm[];
    const int tid = threadIdx.x;
    const int bx = blockIdx.x;
    const int by = blockIdx.y;
    const int lane = tid & 31;
    const int wid = tid >> 5;            // 0..7
    const int wm = (wid & 3) * 64;       // warp row offset (0..192)
    const int wn = (wid >> 2) * 64;      // warp col offset (0 or 64)
    const int g = lane >> 2;
    const int tq = lane & 3;

    const float* Abase = A + (size_t)by * GBM * K;
    const float* Bbase = Bm + bx * GBN;
    const unsigned sm_sa = (unsigned)__cvta_generic_to_shared(sm);

    float acc[4][8][4];
#pragma unroll
    for (int mt = 0; mt < 4; mt++)
#pragma unroll
        for (int nt = 0; nt < 8; nt++)
#pragma unroll
            for (int i = 0; i < 4; i++) acc[mt][nt][i] = 0.f;

    const int ntiles = K / GBK;

    auto issue = [&](int kt, int st) {
        const unsigned as0 = sm_sa + (unsigned)(st * STAGE_FLOATS) * 4u;
        const unsigned bs0 = as0 + GBM * AS_STRIDE * 4u;
#pragma unroll
        for (int i = 0; i < 8; i++) {
            const int cid = tid + i * GEMM_THREADS;   // 0..2047
            const int r = cid >> 3;                   // 0..255
            const int c = (cid & 7) * 4;              // 0..28
            cp16(as0 + (unsigned)(r * AS_STRIDE + c) * 4u,
                 Abase + (size_t)r * K + kt * GBK + c);
        }
#pragma unroll
        for (int i = 0; i < 4; i++) {
            const int cid = tid + i * GEMM_THREADS;   // 0..1023
            const int r = cid >> 5;                   // 0..31
            const int c = (cid & 31) * 4;             // 0..124
            cp16(bs0 + (unsigned)(r * BS_STRIDE + c) * 4u,
                 Bbase + (size_t)(kt * GBK + r) * N + c);
        }
        asm volatile("cp.async.commit_group;\n");
    };

    issue(0, 0);
    issue(1, 1);

    for (int kt = 0; kt < ntiles; kt++) {
        if (kt + 2 < ntiles) issue(kt + 2, (kt + 2) % GEMM_STAGES);
        else asm volatile("cp.async.commit_group;\n");
        asm volatile("cp.async.wait_group 2;\n");
        __syncthreads();

        const float* As = sm + (kt % GEMM_STAGES) * STAGE_FLOATS;
        const float* Bs = As + GBM * AS_STRIDE;

#pragma unroll
        for (int ks = 0; ks < 4; ks++) {
            const int k = ks * 8 + tq;
            unsigned a[4][4], b[8][2];
#pragma unroll
            for (int mt = 0; mt < 4; mt++) {
                const int m = wm + mt * 16 + g;
                a[mt][0] = __float_as_uint(As[m * AS_STRIDE + k]);
                a[mt][1] = __float_as_uint(As[(m + 8) * AS_STRIDE + k]);
                a[mt][2] = __float_as_uint(As[m * AS_STRIDE + k + 4]);
                a[mt][3] = __float_as_uint(As[(m + 8) * AS_STRIDE + k + 4]);
            }
#pragma unroll
            for (int nt = 0; nt < 8; nt++) {
                const int n = wn + nt * 8 + g;
                b[nt][0] = __float_as_uint(Bs[k * BS_STRIDE + n]);
                b[nt][1] = __float_as_uint(Bs[(k + 4) * BS_STRIDE + n]);
            }
#pragma unroll
            for (int mt = 0; mt < 4; mt++)
#pragma unroll
                for (int nt = 0; nt < 8; nt++)
                    mma_tf32(acc[mt][nt], a[mt], b[nt]);
        }
    }

#pragma unroll
    for (int mt = 0; mt < 4; mt++) {
        const int r0 = by * GBM + wm + mt * 16 + g;
#pragma unroll
        for (int nt = 0; nt < 8; nt++) {
            const int c0 = bx * GBN + wn + nt * 8 + 2 * tq;
            *(float2*)(Cm + (size_t)r0 * N + c0) = make_float2(acc[mt][nt][0], acc[mt][nt][1]);
            *(float2*)(Cm + (size_t)(r0 + 8) * N + c0) = make_float2(acc[mt][nt][2], acc[mt][nt][3]);
        }
    }
}

// ---------------- gate: v += 2*sigmoid(x[:, :32] @ Wg)[h] * ve -------------
__global__ __launch_bounds__(256) void gate_kernel(
    const float* __restrict__ x, const float* __restrict__ ve,
    const float* __restrict__ Wg, float* __restrict__ v)
{
    const int m = blockIdx.x;
    const int tid = threadIdx.x;
    __shared__ float xg[32];
    __shared__ float g[H_];

    if (tid < 32) xg[tid] = x[(size_t)m * C_ + tid];
    __syncthreads();
    if (tid < H_) {
        float s = 0.f;
#pragma unroll
        for (int i = 0; i < 32; i++) s += xg[i] * Wg[i * H_ + tid];
        g[tid] = 2.f / (1.f + __expf(-s));
    }
    __syncthreads();

    const size_t base = (size_t)m * C_;
    for (int c = tid; c < C_; c += 256) {
        v[base + c] += g[c >> 7] * ve[base + c];
    }
}

// ---------------- RoPE + RMSNorm for q and k (warp per row,head) -----------
__global__ __launch_bounds__(256) void rope_rms_kernel(
    const float* __restrict__ cosT, const float* __restrict__ sinT,
    float* __restrict__ q, float* __restrict__ k)
{
    const int gw = (blockIdx.x * blockDim.x + threadIdx.x) >> 5;
    const int lane = threadIdx.x & 31;
    const int m = gw / H_;
    const int h = gw % H_;
    const int t = m % T_;

    const float c0 = cosT[t * 64 + lane];
    const float c1 = cosT[t * 64 + lane + 32];
    const float s0 = sinT[t * 64 + lane];
    const float s1 = sinT[t * 64 + lane + 32];

#pragma unroll
    for (int a = 0; a < 2; a++) {
        float* ptr = (a == 0 ? q : k) + (size_t)m * C_ + h * D_;
        float f0 = ptr[lane];
        float f1 = ptr[lane + 32];
        float f2 = ptr[lane + 64];
        float f3 = ptr[lane + 96];
        float r0 =  f0 * c0 + f2 * s0;
        float r2 = -f0 * s0 + f2 * c0;
        float r1 =  f1 * c1 + f3 * s1;
        float r3 = -f1 * s1 + f3 * c1;
        float ss = r0*r0 + r1*r1 + r2*r2 + r3*r3;
#pragma unroll
        for (int off = 16; off; off >>= 1) ss += __shfl_xor_sync(0xffffffffu, ss, off);
        float sc = rsqrtf(ss * (1.f / 128.f) + 1e-6f);
        ptr[lane]      = r0 * sc;
        ptr[lane + 32] = r1 * sc;
        ptr[lane + 64] = r2 * sc;
        ptr[lane + 96] = r3 * sc;
    }
}

// ---------------- tensor-core sliding-window attention ---------------------
#define AQ 128
#define ATK 64
#define KS_STRIDE 132
#define VS_STRIDE 136
#define PS_STRIDE 68
#define SMEM_KS_OFF 0
#define SMEM_VS_OFF (ATK * KS_STRIDE)
#define SMEM_PS_OFF (SMEM_VS_OFF + ATK * VS_STRIDE)
#define SMEM_ATTN_FLOATS (SMEM_PS_OFF + AQ * PS_STRIDE)
#define SMEM_ATTN_BYTES (SMEM_ATTN_FLOATS * 4)

__global__ __launch_bounds__(256) void attn_mma_kernel(
    const float* __restrict__ Q, const float* __restrict__ K,
    const float* __restrict__ V, float* __restrict__ O)
{
    extern __shared__ float sm[];
    float* Ks = sm + SMEM_KS_OFF;
    float* Vs = sm + SMEM_VS_OFF;
    float* Ps = sm + SMEM_PS_OFF;

    const int b = blockIdx.z;
    const int h = blockIdx.y;
    const int t0 = blockIdx.x * AQ;
    const int tid = threadIdx.x;
    const int lane = tid & 31;
    const int wid = tid >> 5;
    const int g = lane >> 2;
    const int tq = lane & 3;
    const int wm = wid * 16;

    unsigned qf[16][4];
    {
        const float* qb = Q + ((size_t)(b * T_ + t0 + wm)) * C_ + h * D_;
#pragma unroll
        for (int ks = 0; ks < 16; ks++) {
            const int c0 = ks * 8 + tq;
            qf[ks][0] = f2tf(qb[(size_t)g * C_ + c0] * SCALE_);
            qf[ks][1] = f2tf(qb[(size_t)(g + 8) * C_ + c0] * SCALE_);
            qf[ks][2] = f2tf(qb[(size_t)g * C_ + c0 + 4] * SCALE_);
            qf[ks][3] = f2tf(qb[(size_t)(g + 8) * C_ + c0 + 4] * SCALE_);
        }
    }

    float o[16][4];
#pragma unroll
    for (int nt = 0; nt < 16; nt++)
#pragma unroll
        for (int i = 0; i < 4; i++) o[nt][i] = 0.f;

    float m0 = -1e30f, m1 = -1e30f, l0 = 0.f, l1 = 0.f;
    const int trow0 = t0 + wm + g;
    const int trow1 = trow0 + 8;

    int lo = t0 - W_;
    if (lo < 0) lo = 0;

    for (int ks0 = lo; ks0 < t0 + AQ; ks0 += ATK) {
#pragma unroll
        for (int it = 0; it < 8; it++) {
            const int idx = tid + it * 256;
            const int row = idx >> 5;
            const int c4 = (idx & 31) * 4;
            const size_t gbase = ((size_t)(b * T_ + ks0 + row)) * C_ + h * D_ + c4;
            float4 kv = *(const float4*)(K + gbase);
            float4 vv = *(const float4*)(V + gbase);
            float* kd = Ks + row * KS_STRIDE + c4;
            kd[0] = __uint_as_float(f2tf(kv.x));
            kd[1] = __uint_as_float(f2tf(kv.y));
            kd[2] = __uint_as_float(f2tf(kv.z));
            kd[3] = __uint_as_float(f2tf(kv.w));
            float* vd = Vs + row * VS_STRIDE + c4;
            vd[0] = __uint_as_float(f2tf(vv.x));
            vd[1] = __uint_as_float(f2tf(vv.y));
            vd[2] = __uint_as_float(f2tf(vv.z));
            vd[3] = __uint_as_float(f2tf(vv.w));
        }
        __syncthreads();

        float s[8][4];
#pragma unroll
        for (int nt = 0; nt < 8; nt++)
#pragma unroll
            for (int i = 0; i < 4; i++) s[nt][i] = 0.f;

#pragma unroll
        for (int ksp = 0; ksp < 16; ksp++) {
            const int k = ksp * 8 + tq;
            unsigned bfr[8][2];
#pragma unroll
            for (int nt = 0; nt < 8; nt++) {
                const int n = nt * 8 + g;
                bfr[nt][0] = __float_as_uint(Ks[n * KS_STRIDE + k]);
                bfr[nt][1] = __float_as_uint(Ks[n * KS_STRIDE + k + 4]);
            }
#pragma unroll
            for (int nt = 0; nt < 8; nt++)
                mma_tf32(s[nt], qf[ksp], bfr[nt]);
        }

        float mt0 = -1e30f, mt1 = -1e30f;
#pragma unroll
        for (int nt = 0; nt < 8; nt++) {
            const int kt0 = ks0 + nt * 8 + 2 * tq;
            const int kt1 = kt0 + 1;
            s[nt][0] = (kt0 <= trow0 && kt0 >= trow0 - W_) ? s[nt][0] : -1e30f;
            s[nt][1] = (kt1 <= trow0 && kt1 >= trow0 - W_) ? s[nt][1] : -1e30f;
            s[nt][2] = (kt0 <= trow1 && kt0 >= trow1 - W_) ? s[nt][2] : -1e30f;
            s[nt][3] = (kt1 <= trow1 && kt1 >= trow1 - W_) ? s[nt][3] : -1e30f;
            mt0 = fmaxf(mt0, fmaxf(s[nt][0], s[nt][1]));
            mt1 = fmaxf(mt1, fmaxf(s[nt][2], s[nt][3]));
        }
        mt0 = fmaxf(mt0, __shfl_xor_sync(0xffffffffu, mt0, 1));
        mt0 = fmaxf(mt0, __shfl_xor_sync(0xffffffffu, mt0, 2));
        mt1 = fmaxf(mt1, __shfl_xor_sync(0xffffffffu, mt1, 1));
        mt1 = fmaxf(mt1, __shfl_xor_sync(0xffffffffu, mt1, 2));

        const float mn0 = fmaxf(m0, mt0);
        const float mn1 = fmaxf(m1, mt1);
        const float corr0 = __expf(m0 - mn0);
        const float corr1 = __expf(m1 - mn1);
        m0 = mn0; m1 = mn1;

        float ls0 = 0.f, ls1 = 0.f;
        float* pw0 = Ps + (wm + g) * PS_STRIDE;
        float* pw1 = Ps + (wm + g + 8) * PS_STRIDE;
#pragma unroll
        for (int nt = 0; nt < 8; nt++) {
            const int c = nt * 8 + 2 * tq;
            float p00 = (s[nt][0] > -1e29f) ? __expf(s[nt][0] - mn0) : 0.f;
            float p01 = (s[nt][1] > -1e29f) ? __expf(s[nt][1] - mn0) : 0.f;
            float p10 = (s[nt][2] > -1e29f) ? __expf(s[nt][2] - mn1) : 0.f;
            float p11 = (s[nt][3] > -1e29f) ? __expf(s[nt][3] - mn1) : 0.f;
            ls0 += p00 + p01;
            ls1 += p10 + p11;
            pw0[c]     = __uint_as_float(f2tf(p00));
            pw0[c + 1] = __uint_as_float(f2tf(p01));
            pw1[c]     = __uint_as_float(f2tf(p10));
            pw1[c + 1] = __uint_as_float(f2tf(p11));
        }
        ls0 += __shfl_xor_sync(0xffffffffu, ls0, 1);
        ls0 += __shfl_xor_sync(0xffffffffu, ls0, 2);
        ls1 += __shfl_xor_sync(0xffffffffu, ls1, 1);
        ls1 += __shfl_xor_sync(0xffffffffu, ls1, 2);
        l0 = l0 * corr0 + ls0;
        l1 = l1 * corr1 + ls1;

#pragma unroll
        for (int nt = 0; nt < 16; nt++) {
            o[nt][0] *= corr0; o[nt][1] *= corr0;
            o[nt][2] *= corr1; o[nt][3] *= corr1;
        }

        __syncwarp();

#pragma unroll
        for (int ksp = 0; ksp < 8; ksp++) {
            const int k = ksp * 8 + tq;
            unsigned a[4];
            a[0] = __float_as_uint(Ps[(wm + g) * PS_STRIDE + k]);
            a[1] = __float_as_uint(Ps[(wm + g + 8) * PS_STRIDE + k]);
            a[2] = __float_as_uint(Ps[(wm + g) * PS_STRIDE + k + 4]);
            a[3] = __float_as_uint(Ps[(wm + g + 8) * PS_STRIDE + k + 4]);
            unsigned bfr[2];
#pragma unroll
            for (int nt = 0; nt < 16; nt++) {
                const int n = nt * 8 + g;
                bfr[0] = __float_as_uint(Vs[k * VS_STRIDE + n]);
                bfr[1] = __float_as_uint(Vs[(k + 4) * VS_STRIDE + n]);
                mma_tf32(o[nt], a, bfr);
            }
        }
        __syncthreads();
    }

    // epilogue: write tf32-rounded output (proj GEMM reads it raw)
    const float inv0 = 1.f / l0;
    const float inv1 = 1.f / l1;
    float* ob0 = O + ((size_t)(b * T_ + trow0)) * C_ + h * D_;
    float* ob1 = O + ((size_t)(b * T_ + trow1)) * C_ + h * D_;
#pragma unroll
    for (int nt = 0; nt < 16; nt++) {
        const int c = nt * 8 + 2 * tq;
        *(float2*)(ob0 + c) = make_float2(__uint_as_float(f2tf(o[nt][0] * inv0)),
                                          __uint_as_float(f2tf(o[nt][1] * inv0)));
        *(float2*)(ob1 + c) = make_float2(__uint_as_float(f2tf(o[nt][2] * inv1)),
                                          __uint_as_float(f2tf(o[nt][3] * inv1)));
    }
}

// ---------------- launch ---------------------------------------------------
extern "C" void kernel_launch(void* const* d_in, const int* in_sizes, int n_in,
                              void* d_out, int out_size)
{
    const float* x     = (const float*)d_in[0];
    const float* ve    = (const float*)d_in[1];
    const float* cosT  = (const float*)d_in[2];
    const float* sinT  = (const float*)d_in[3];
    const float* Wq    = (const float*)d_in[4];
    const float* Wk    = (const float*)d_in[5];
    const float* Wv    = (const float*)d_in[6];
    const float* Wproj = (const float*)d_in[7];
    const float* Wg    = (const float*)d_in[8];
    float* out = (float*)d_out;

    float *q, *k, *v, *o, *xt, *wq, *wk, *wv, *wp;
    cudaGetSymbolAddress((void**)&q, g_q);
    cudaGetSymbolAddress((void**)&k, g_k);
    cudaGetSymbolAddress((void**)&v, g_v);
    cudaGetSymbolAddress((void**)&o, g_o);
    cudaGetSymbolAddress((void**)&xt, g_xt);
    cudaGetSymbolAddress((void**)&wq, g_wq);
    cudaGetSymbolAddress((void**)&wk, g_wk);
    cudaGetSymbolAddress((void**)&wv, g_wv);
    cudaGetSymbolAddress((void**)&wp, g_wp);

    static int attr_set = 0;
    if (!attr_set) {
        cudaFuncSetAttribute(attn_mma_kernel,
                             cudaFuncAttributeMaxDynamicSharedMemorySize,
                             SMEM_ATTN_BYTES);
        cudaFuncSetAttribute(tf32_gemm_pipe,
                             cudaFuncAttributeMaxDynamicSharedMemorySize,
                             GEMM_SMEM_BYTES);
        attr_set = 1;
    }

    // tf32 pre-round: x and weights
    const int nx4 = (M_ * C_) / 4;
    const int nw4 = (C_ * C_) / 4;
    round_tf32_kernel<<<nx4 / 256, 256>>>(x, xt, nx4);
    round_tf32_kernel<<<nw4 / 256, 256>>>(Wq, wq, nw4);
    round_tf32_kernel<<<nw4 / 256, 256>>>(Wk, wk, nw4);
    round_tf32_kernel<<<nw4 / 256, 256>>>(Wv, wv, nw4);
    round_tf32_kernel<<<nw4 / 256, 256>>>(Wproj, wp, nw4);

    dim3 gemm_grid(C_ / GBN, M_ / GBM);
    tf32_gemm_pipe<<<gemm_grid, GEMM_THREADS, GEMM_SMEM_BYTES>>>(xt, wq, q, M_, C_, C_);
    tf32_gemm_pipe<<<gemm_grid, GEMM_THREADS, GEMM_SMEM_BYTES>>>(xt, wk, k, M_, C_, C_);
    tf32_gemm_pipe<<<gemm_grid, GEMM_THREADS, GEMM_SMEM_BYTES>>>(xt, wv, v, M_, C_, C_);

    gate_kernel<<<M_, 256>>>(x, ve, Wg, v);
    rope_rms_kernel<<<(M_ * H_) / 8, 256>>>(cosT, sinT, q, k);

    dim3 attn_grid(T_ / AQ, H_, B_);
    attn_mma_kernel<<<attn_grid, 256, SMEM_ATTN_BYTES>>>(q, k, v, o);

    tf32_gemm_pipe<<<gemm_grid, GEMM_THREADS, GEMM_SMEM_BYTES>>>(o, wp, out, M_, C_, C_);
}

// round 11
// speedup vs baseline: 1.1059x; 1.0522x over previous
#include <cuda_runtime.h>
#include <cuda_bf16.h>
#include <math.h>

// Problem constants
#define B_ 2
#define T_ 4096
#define C_ 2048
#define H_ 16
#define D_ 128
#define W_ 1024
#define M_ (B_*T_)          // 8192 rows
#define SCALE_ (0.08838834764831845f)   // 1/sqrt(128)

// ---------------- scratch (device globals; no cudaMalloc allowed) ----------
__device__ float g_q[(size_t)M_ * C_];
__device__ float g_k[(size_t)M_ * C_];
__device__ float g_v[(size_t)M_ * C_];
__device__ float g_o[(size_t)M_ * C_];
__device__ float g_xt[(size_t)M_ * C_];       // tf32-rounded x
__device__ float g_wq[(size_t)C_ * C_];
__device__ float g_wk[(size_t)C_ * C_];
__device__ float g_wv[(size_t)C_ * C_];
__device__ float g_wp[(size_t)C_ * C_];

// ---------------- common helpers -------------------------------------------
__device__ __forceinline__ unsigned f2tf(float f) {
    unsigned u;
    asm("cvt.rna.tf32.f32 %0, %1;" : "=r"(u) : "f"(f));
    return u;
}

__device__ __forceinline__ void mma_tf32(float* c, const unsigned* a, const unsigned* b) {
    asm volatile(
        "mma.sync.aligned.m16n8k8.row.col.f32.tf32.tf32.f32 "
        "{%0,%1,%2,%3}, {%4,%5,%6,%7}, {%8,%9}, {%0,%1,%2,%3};"
        : "+f"(c[0]), "+f"(c[1]), "+f"(c[2]), "+f"(c[3])
        : "r"(a[0]), "r"(a[1]), "r"(a[2]), "r"(a[3]), "r"(b[0]), "r"(b[1]));
}

__device__ __forceinline__ void cp16(unsigned s_addr, const float* g) {
    asm volatile("cp.async.cg.shared.global [%0], [%1], 16;\n" :: "r"(s_addr), "l"(g));
}

// ---------------- tf32 rounding pre-pass -----------------------------------
__global__ __launch_bounds__(256) void round_tf32_kernel(
    const float* __restrict__ in, float* __restrict__ out, int n4)
{
    int i = blockIdx.x * blockDim.x + threadIdx.x;
    if (i < n4) {
        float4 v = ((const float4*)in)[i];
        v.x = __uint_as_float(f2tf(v.x));
        v.y = __uint_as_float(f2tf(v.y));
        v.z = __uint_as_float(f2tf(v.z));
        v.w = __uint_as_float(f2tf(v.w));
        ((float4*)out)[i] = v;
    }
}

// ---------------- TF32 GEMM, 3-stage cp.async, 2 CTAs/SM -------------------
// C = A[MxK] * B[KxN]; A,B pre-rounded to tf32 values in fp32 storage.
// Round-7 tiling (128x128 CTA, 8 warps in 2x4, each 64x32) — the best
// measured config — but 3 stages (107,520 B) so TWO CTAs co-reside per SM:
// 4 warps/SMSP to hide the cp.async/barrier/LDS latency that limited
// round 7 (measured 3.5x over the issue-model floor at 1 CTA/SM).
// Depth-1 prefetch: issue(kt+1) writes stage (kt+1)%3, last consumed at
// compute(kt-2) -> safe behind the per-iteration __syncthreads().
#define GBM 128
#define GBN 128
#define GBK 32
#define AS_STRIDE 36     // 128x36 floats
#define BS_STRIDE 136    // 32x136 floats
#define STAGE_FLOATS (GBM * AS_STRIDE + GBK * BS_STRIDE)   // 4608+4352 = 8960
#define GEMM_STAGES 3
#define GEMM_SMEM_BYTES (GEMM_STAGES * STAGE_FLOATS * 4)   // 107520
#define GEMM_THREADS 256

__global__ __launch_bounds__(GEMM_THREADS, 2) void tf32_gemm_pipe(
    const float* __restrict__ A, const float* __restrict__ Bm,
    float* __restrict__ Cm, int M, int N, int K)
{
    extern __shared__ float sm[];
    const int tid = threadIdx.x;
    const int bx = blockIdx.x;
    const int by = blockIdx.y;
    const int lane = tid & 31;
    const int wid = tid >> 5;
    const int wm = (wid & 1) * 64;
    const int wn = (wid >> 1) * 32;
    const int g = lane >> 2;
    const int tq = lane & 3;

    const float* Abase = A + (size_t)by * GBM * K;
    const float* Bbase = Bm + bx * GBN;
    const unsigned sm_sa = (unsigned)__cvta_generic_to_shared(sm);

    float acc[4][4][4];
#pragma unroll
    for (int mt = 0; mt < 4; mt++)
#pragma unroll
        for (int nt = 0; nt < 4; nt++)
#pragma unroll
            for (int i = 0; i < 4; i++) acc[mt][nt][i] = 0.f;

    const int ntiles = K / GBK;

    auto issue = [&](int kt, int st) {
        const unsigned as0 = sm_sa + (unsigned)(st * STAGE_FLOATS) * 4u;
        const unsigned bs0 = as0 + GBM * AS_STRIDE * 4u;
#pragma unroll
        for (int i = 0; i < 4; i++) {
            const int cid = tid + i * GEMM_THREADS;   // 0..1023
            const int r = cid >> 3;                   // 0..127
            const int c = (cid & 7) * 4;              // 0..28
            cp16(as0 + (unsigned)(r * AS_STRIDE + c) * 4u,
                 Abase + (size_t)r * K + kt * GBK + c);
        }
#pragma unroll
        for (int i = 0; i < 4; i++) {
            const int cid = tid + i * GEMM_THREADS;
            const int r = cid >> 5;                   // 0..31
            const int c = (cid & 31) * 4;             // 0..124
            cp16(bs0 + (unsigned)(r * BS_STRIDE + c) * 4u,
                 Bbase + (size_t)(kt * GBK + r) * N + c);
        }
        asm volatile("cp.async.commit_group;\n");
    };

    issue(0, 0);

    for (int kt = 0; kt < ntiles; kt++) {
        if (kt + 1 < ntiles) issue(kt + 1, (kt + 1) % GEMM_STAGES);
        else asm volatile("cp.async.commit_group;\n");
        asm volatile("cp.async.wait_group 1;\n");
        __syncthreads();

        const float* As = sm + (kt % GEMM_STAGES) * STAGE_FLOATS;
        const float* Bs = As + GBM * AS_STRIDE;

#pragma unroll
        for (int ks = 0; ks < 4; ks++) {
            const int k = ks * 8 + tq;
            unsigned a[4][4], b[4][2];
#pragma unroll
            for (int mt = 0; mt < 4; mt++) {
                const int m = wm + mt * 16 + g;
                a[mt][0] = __float_as_uint(As[m * AS_STRIDE + k]);
                a[mt][1] = __float_as_uint(As[(m + 8) * AS_STRIDE + k]);
                a[mt][2] = __float_as_uint(As[m * AS_STRIDE + k + 4]);
                a[mt][3] = __float_as_uint(As[(m + 8) * AS_STRIDE + k + 4]);
            }
#pragma unroll
            for (int nt = 0; nt < 4; nt++) {
                const int n = wn + nt * 8 + g;
                b[nt][0] = __float_as_uint(Bs[k * BS_STRIDE + n]);
                b[nt][1] = __float_as_uint(Bs[(k + 4) * BS_STRIDE + n]);
            }
#pragma unroll
            for (int mt = 0; mt < 4; mt++)
#pragma unroll
                for (int nt = 0; nt < 4; nt++)
                    mma_tf32(acc[mt][nt], a[mt], b[nt]);
        }
        __syncthreads();
    }

#pragma unroll
    for (int mt = 0; mt < 4; mt++) {
        const int r0 = by * GBM + wm + mt * 16 + g;
#pragma unroll
        for (int nt = 0; nt < 4; nt++) {
            const int c0 = bx * GBN + wn + nt * 8 + 2 * tq;
            *(float2*)(Cm + (size_t)r0 * N + c0) = make_float2(acc[mt][nt][0], acc[mt][nt][1]);
            *(float2*)(Cm + (size_t)(r0 + 8) * N + c0) = make_float2(acc[mt][nt][2], acc[mt][nt][3]);
        }
    }
}

// ---------------- gate: v += 2*sigmoid(x[:, :32] @ Wg)[h] * ve -------------
__global__ __launch_bounds__(256) void gate_kernel(
    const float* __restrict__ x, const float* __restrict__ ve,
    const float* __restrict__ Wg, float* __restrict__ v)
{
    const int m = blockIdx.x;
    const int tid = threadIdx.x;
    __shared__ float xg[32];
    __shared__ float g[H_];

    if (tid < 32) xg[tid] = x[(size_t)m * C_ + tid];
    __syncthreads();
    if (tid < H_) {
        float s = 0.f;
#pragma unroll
        for (int i = 0; i < 32; i++) s += xg[i] * Wg[i * H_ + tid];
        g[tid] = 2.f / (1.f + __expf(-s));
    }
    __syncthreads();

    const size_t base = (size_t)m * C_;
    for (int c = tid; c < C_; c += 256) {
        v[base + c] += g[c >> 7] * ve[base + c];
    }
}

// ---------------- RoPE + RMSNorm for q and k (warp per row,head) -----------
__global__ __launch_bounds__(256) void rope_rms_kernel(
    const float* __restrict__ cosT, const float* __restrict__ sinT,
    float* __restrict__ q, float* __restrict__ k)
{
    const int gw = (blockIdx.x * blockDim.x + threadIdx.x) >> 5;
    const int lane = threadIdx.x & 31;
    const int m = gw / H_;
    const int h = gw % H_;
    const int t = m % T_;

    const float c0 = cosT[t * 64 + lane];
    const float c1 = cosT[t * 64 + lane + 32];
    const float s0 = sinT[t * 64 + lane];
    const float s1 = sinT[t * 64 + lane + 32];

#pragma unroll
    for (int a = 0; a < 2; a++) {
        float* ptr = (a == 0 ? q : k) + (size_t)m * C_ + h * D_;
        float f0 = ptr[lane];
        float f1 = ptr[lane + 32];
        float f2 = ptr[lane + 64];
        float f3 = ptr[lane + 96];
        float r0 =  f0 * c0 + f2 * s0;
        float r2 = -f0 * s0 + f2 * c0;
        float r1 =  f1 * c1 + f3 * s1;
        float r3 = -f1 * s1 + f3 * c1;
        float ss = r0*r0 + r1*r1 + r2*r2 + r3*r3;
#pragma unroll
        for (int off = 16; off; off >>= 1) ss += __shfl_xor_sync(0xffffffffu, ss, off);
        float sc = rsqrtf(ss * (1.f / 128.f) + 1e-6f);
        ptr[lane]      = r0 * sc;
        ptr[lane + 32] = r1 * sc;
        ptr[lane + 64] = r2 * sc;
        ptr[lane + 96] = r3 * sc;
    }
}

// ---------------- tensor-core sliding-window attention ---------------------
#define AQ 128
#define ATK 64
#define KS_STRIDE 132
#define VS_STRIDE 136
#define PS_STRIDE 68
#define SMEM_KS_OFF 0
#define SMEM_VS_OFF (ATK * KS_STRIDE)
#define SMEM_PS_OFF (SMEM_VS_OFF + ATK * VS_STRIDE)
#define SMEM_ATTN_FLOATS (SMEM_PS_OFF + AQ * PS_STRIDE)
#define SMEM_ATTN_BYTES (SMEM_ATTN_FLOATS * 4)

__global__ __launch_bounds__(256) void attn_mma_kernel(
    const float* __restrict__ Q, const float* __restrict__ K,
    const float* __restrict__ V, float* __restrict__ O)
{
    extern __shared__ float sm[];
    float* Ks = sm + SMEM_KS_OFF;
    float* Vs = sm + SMEM_VS_OFF;
    float* Ps = sm + SMEM_PS_OFF;

    const int b = blockIdx.z;
    const int h = blockIdx.y;
    const int t0 = blockIdx.x * AQ;
    const int tid = threadIdx.x;
    const int lane = tid & 31;
    const int wid = tid >> 5;
    const int g = lane >> 2;
    const int tq = lane & 3;
    const int wm = wid * 16;

    unsigned qf[16][4];
    {
        const float* qb = Q + ((size_t)(b * T_ + t0 + wm)) * C_ + h * D_;
#pragma unroll
        for (int ks = 0; ks < 16; ks++) {
            const int c0 = ks * 8 + tq;
            qf[ks][0] = f2tf(qb[(size_t)g * C_ + c0] * SCALE_);
            qf[ks][1] = f2tf(qb[(size_t)(g + 8) * C_ + c0] * SCALE_);
            qf[ks][2] = f2tf(qb[(size_t)g * C_ + c0 + 4] * SCALE_);
            qf[ks][3] = f2tf(qb[(size_t)(g + 8) * C_ + c0 + 4] * SCALE_);
        }
    }

    float o[16][4];
#pragma unroll
    for (int nt = 0; nt < 16; nt++)
#pragma unroll
        for (int i = 0; i < 4; i++) o[nt][i] = 0.f;

    float m0 = -1e30f, m1 = -1e30f, l0 = 0.f, l1 = 0.f;
    const int trow0 = t0 + wm + g;
    const int trow1 = trow0 + 8;

    int lo = t0 - W_;
    if (lo < 0) lo = 0;

    for (int ks0 = lo; ks0 < t0 + AQ; ks0 += ATK) {
#pragma unroll
        for (int it = 0; it < 8; it++) {
            const int idx = tid + it * 256;
            const int row = idx >> 5;
            const int c4 = (idx & 31) * 4;
            const size_t gbase = ((size_t)(b * T_ + ks0 + row)) * C_ + h * D_ + c4;
            float4 kv = *(const float4*)(K + gbase);
            float4 vv = *(const float4*)(V + gbase);
            float* kd = Ks + row * KS_STRIDE + c4;
            kd[0] = __uint_as_float(f2tf(kv.x));
            kd[1] = __uint_as_float(f2tf(kv.y));
            kd[2] = __uint_as_float(f2tf(kv.z));
            kd[3] = __uint_as_float(f2tf(kv.w));
            float* vd = Vs + row * VS_STRIDE + c4;
            vd[0] = __uint_as_float(f2tf(vv.x));
            vd[1] = __uint_as_float(f2tf(vv.y));
            vd[2] = __uint_as_float(f2tf(vv.z));
            vd[3] = __uint_as_float(f2tf(vv.w));
        }
        __syncthreads();

        float s[8][4];
#pragma unroll
        for (int nt = 0; nt < 8; nt++)
#pragma unroll
            for (int i = 0; i < 4; i++) s[nt][i] = 0.f;

#pragma unroll
        for (int ksp = 0; ksp < 16; ksp++) {
            const int k = ksp * 8 + tq;
            unsigned bfr[8][2];
#pragma unroll
            for (int nt = 0; nt < 8; nt++) {
                const int n = nt * 8 + g;
                bfr[nt][0] = __float_as_uint(Ks[n * KS_STRIDE + k]);
                bfr[nt][1] = __float_as_uint(Ks[n * KS_STRIDE + k + 4]);
            }
#pragma unroll
            for (int nt = 0; nt < 8; nt++)
                mma_tf32(s[nt], qf[ksp], bfr[nt]);
        }

        float mt0 = -1e30f, mt1 = -1e30f;
#pragma unroll
        for (int nt = 0; nt < 8; nt++) {
            const int kt0 = ks0 + nt * 8 + 2 * tq;
            const int kt1 = kt0 + 1;
            s[nt][0] = (kt0 <= trow0 && kt0 >= trow0 - W_) ? s[nt][0] : -1e30f;
            s[nt][1] = (kt1 <= trow0 && kt1 >= trow0 - W_) ? s[nt][1] : -1e30f;
            s[nt][2] = (kt0 <= trow1 && kt0 >= trow1 - W_) ? s[nt][2] : -1e30f;
            s[nt][3] = (kt1 <= trow1 && kt1 >= trow1 - W_) ? s[nt][3] : -1e30f;
            mt0 = fmaxf(mt0, fmaxf(s[nt][0], s[nt][1]));
            mt1 = fmaxf(mt1, fmaxf(s[nt][2], s[nt][3]));
        }
        mt0 = fmaxf(mt0, __shfl_xor_sync(0xffffffffu, mt0, 1));
        mt0 = fmaxf(mt0, __shfl_xor_sync(0xffffffffu, mt0, 2));
        mt1 = fmaxf(mt1, __shfl_xor_sync(0xffffffffu, mt1, 1));
        mt1 = fmaxf(mt1, __shfl_xor_sync(0xffffffffu, mt1, 2));

        const float mn0 = fmaxf(m0, mt0);
        const float mn1 = fmaxf(m1, mt1);
        const float corr0 = __expf(m0 - mn0);
        const float corr1 = __expf(m1 - mn1);
        m0 = mn0; m1 = mn1;

        float ls0 = 0.f, ls1 = 0.f;
        float* pw0 = Ps + (wm + g) * PS_STRIDE;
        float* pw1 = Ps + (wm + g + 8) * PS_STRIDE;
#pragma unroll
        for (int nt = 0; nt < 8; nt++) {
            const int c = nt * 8 + 2 * tq;
            float p00 = (s[nt][0] > -1e29f) ? __expf(s[nt][0] - mn0) : 0.f;
            float p01 = (s[nt][1] > -1e29f) ? __expf(s[nt][1] - mn0) : 0.f;
            float p10 = (s[nt][2] > -1e29f) ? __expf(s[nt][2] - mn1) : 0.f;
            float p11 = (s[nt][3] > -1e29f) ? __expf(s[nt][3] - mn1) : 0.f;
            ls0 += p00 + p01;
            ls1 += p10 + p11;
            pw0[c]     = __uint_as_float(f2tf(p00));
            pw0[c + 1] = __uint_as_float(f2tf(p01));
            pw1[c]     = __uint_as_float(f2tf(p10));
            pw1[c + 1] = __uint_as_float(f2tf(p11));
        }
        ls0 += __shfl_xor_sync(0xffffffffu, ls0, 1);
        ls0 += __shfl_xor_sync(0xffffffffu, ls0, 2);
        ls1 += __shfl_xor_sync(0xffffffffu, ls1, 1);
        ls1 += __shfl_xor_sync(0xffffffffu, ls1, 2);
        l0 = l0 * corr0 + ls0;
        l1 = l1 * corr1 + ls1;

#pragma unroll
        for (int nt = 0; nt < 16; nt++) {
            o[nt][0] *= corr0; o[nt][1] *= corr0;
            o[nt][2] *= corr1; o[nt][3] *= corr1;
        }

        __syncwarp();

#pragma unroll
        for (int ksp = 0; ksp < 8; ksp++) {
            const int k = ksp * 8 + tq;
            unsigned a[4];
            a[0] = __float_as_uint(Ps[(wm + g) * PS_STRIDE + k]);
            a[1] = __float_as_uint(Ps[(wm + g + 8) * PS_STRIDE + k]);
            a[2] = __float_as_uint(Ps[(wm + g) * PS_STRIDE + k + 4]);
            a[3] = __float_as_uint(Ps[(wm + g + 8) * PS_STRIDE + k + 4]);
            unsigned bfr[2];
#pragma unroll
            for (int nt = 0; nt < 16; nt++) {
                const int n = nt * 8 + g;
                bfr[0] = __float_as_uint(Vs[k * VS_STRIDE + n]);
                bfr[1] = __float_as_uint(Vs[(k + 4) * VS_STRIDE + n]);
                mma_tf32(o[nt], a, bfr);
            }
        }
        __syncthreads();
    }

    // epilogue: write tf32-rounded output (proj GEMM reads it raw)
    const float inv0 = 1.f / l0;
    const float inv1 = 1.f / l1;
    float* ob0 = O + ((size_t)(b * T_ + trow0)) * C_ + h * D_;
    float* ob1 = O + ((size_t)(b * T_ + trow1)) * C_ + h * D_;
#pragma unroll
    for (int nt = 0; nt < 16; nt++) {
        const int c = nt * 8 + 2 * tq;
        *(float2*)(ob0 + c) = make_float2(__uint_as_float(f2tf(o[nt][0] * inv0)),
                                          __uint_as_float(f2tf(o[nt][1] * inv0)));
        *(float2*)(ob1 + c) = make_float2(__uint_as_float(f2tf(o[nt][2] * inv1)),
                                          __uint_as_float(f2tf(o[nt][3] * inv1)));
    }
}

// ---------------- launch ---------------------------------------------------
extern "C" void kernel_launch(void* const* d_in, const int* in_sizes, int n_in,
                              void* d_out, int out_size)
{
    const float* x     = (const float*)d_in[0];
    const float* ve    = (const float*)d_in[1];
    const float* cosT  = (const float*)d_in[2];
    const float* sinT  = (const float*)d_in[3];
    const float* Wq    = (const float*)d_in[4];
    const float* Wk    = (const float*)d_in[5];
    const float* Wv    = (const float*)d_in[6];
    const float* Wproj = (const float*)d_in[7];
    const float* Wg    = (const float*)d_in[8];
    float* out = (float*)d_out;

    float *q, *k, *v, *o, *xt, *wq, *wk, *wv, *wp;
    cudaGetSymbolAddress((void**)&q, g_q);
    cudaGetSymbolAddress((void**)&k, g_k);
    cudaGetSymbolAddress((void**)&v, g_v);
    cudaGetSymbolAddress((void**)&o, g_o);
    cudaGetSymbolAddress((void**)&xt, g_xt);
    cudaGetSymbolAddress((void**)&wq, g_wq);
    cudaGetSymbolAddress((void**)&wk, g_wk);
    cudaGetSymbolAddress((void**)&wv, g_wv);
    cudaGetSymbolAddress((void**)&wp, g_wp);

    static int attr_set = 0;
    if (!attr_set) {
        cudaFuncSetAttribute(attn_mma_kernel,
                             cudaFuncAttributeMaxDynamicSharedMemorySize,
                             SMEM_ATTN_BYTES);
        cudaFuncSetAttribute(tf32_gemm_pipe,
                             cudaFuncAttributeMaxDynamicSharedMemorySize,
                             GEMM_SMEM_BYTES);
        attr_set = 1;
    }

    // tf32 pre-round: x and weights
    const int nx4 = (M_ * C_) / 4;
    const int nw4 = (C_ * C_) / 4;
    round_tf32_kernel<<<nx4 / 256, 256>>>(x, xt, nx4);
    round_tf32_kernel<<<nw4 / 256, 256>>>(Wq, wq, nw4);
    round_tf32_kernel<<<nw4 / 256, 256>>>(Wk, wk, nw4);
    round_tf32_kernel<<<nw4 / 256, 256>>>(Wv, wv, nw4);
    round_tf32_kernel<<<nw4 / 256, 256>>>(Wproj, wp, nw4);

    dim3 gemm_grid(C_ / GBN, M_ / GBM);
    tf32_gemm_pipe<<<gemm_grid, GEMM_THREADS, GEMM_SMEM_BYTES>>>(xt, wq, q, M_, C_, C_);
    tf32_gemm_pipe<<<gemm_grid, GEMM_THREADS, GEMM_SMEM_BYTES>>>(xt, wk, k, M_, C_, C_);
    tf32_gemm_pipe<<<gemm_grid, GEMM_THREADS, GEMM_SMEM_BYTES>>>(xt, wv, v, M_, C_, C_);

    gate_kernel<<<M_, 256>>>(x, ve, Wg, v);
    rope_rms_kernel<<<(M_ * H_) / 8, 256>>>(cosT, sinT, q, k);

    dim3 attn_grid(T_ / AQ, H_, B_);
    attn_mma_kernel<<<attn_grid, 256, SMEM_ATTN_BYTES>>>(q, k, v, o);

    tf32_gemm_pipe<<<gemm_grid, GEMM_THREADS, GEMM_SMEM_BYTES>>>(o, wp, out, M_, C_, C_);
}

// round 14
// speedup vs baseline: 1.1472x; 1.0373x over previous
#include <cuda_runtime.h>
#include <cuda_bf16.h>
#include <math.h>
#include <stdint.h>

// Problem constants
#define B_ 2
#define T_ 4096
#define C_ 2048
#define H_ 16
#define D_ 128
#define W_ 1024
#define M_ (B_*T_)          // 8192 rows
#define SCALE_ (0.08838834764831845f)   // 1/sqrt(128)

// ---------------- scratch (device globals; no cudaMalloc allowed) ----------
__device__ float g_q[(size_t)M_ * C_];
__device__ float g_k[(size_t)M_ * C_];
__device__ float g_v[(size_t)M_ * C_];
__device__ float g_o[(size_t)M_ * C_];
__device__ float g_xt[(size_t)M_ * C_];       // tf32-rounded x
__device__ float g_wq[(size_t)C_ * C_];
__device__ float g_wk[(size_t)C_ * C_];
__device__ float g_wv[(size_t)C_ * C_];
__device__ float g_wp[(size_t)C_ * C_];

// ---------------- common helpers -------------------------------------------
__device__ __forceinline__ unsigned f2tf(float f) {
    unsigned u;
    asm("cvt.rna.tf32.f32 %0, %1;" : "=r"(u) : "f"(f));
    return u;
}

__device__ __forceinline__ void mma_tf32(float* c, const unsigned* a, const unsigned* b) {
    asm volatile(
        "mma.sync.aligned.m16n8k8.row.col.f32.tf32.tf32.f32 "
        "{%0,%1,%2,%3}, {%4,%5,%6,%7}, {%8,%9}, {%0,%1,%2,%3};"
        : "+f"(c[0]), "+f"(c[1]), "+f"(c[2]), "+f"(c[3])
        : "r"(a[0]), "r"(a[1]), "r"(a[2]), "r"(a[3]), "r"(b[0]), "r"(b[1]));
}

__device__ __forceinline__ void cp16(unsigned s_addr, const float* g) {
    asm volatile("cp.async.cg.shared.global [%0], [%1], 16;\n" :: "r"(s_addr), "l"(g));
}

// ldmatrix x4 (b16 view) -> exactly the tf32 m16n8k8 A fragment
__device__ __forceinline__ void ldsm_x4(unsigned addr, unsigned* r) {
    asm volatile(
        "ldmatrix.sync.aligned.m8n8.x4.shared.b16 {%0,%1,%2,%3}, [%4];"
        : "=r"(r[0]), "=r"(r[1]), "=r"(r[2]), "=r"(r[3]) : "r"(addr));
}

// ---------------- tf32 rounding pre-passes ----------------------------------
__global__ __launch_bounds__(256) void round_tf32_kernel(
    const float* __restrict__ in, float* __restrict__ out, int n4)
{
    int i = blockIdx.x * blockDim.x + threadIdx.x;
    if (i < n4) {
        float4 v = ((const float4*)in)[i];
        v.x = __uint_as_float(f2tf(v.x));
        v.y = __uint_as_float(f2tf(v.y));
        v.z = __uint_as_float(f2tf(v.z));
        v.w = __uint_as_float(f2tf(v.w));
        ((float4*)out)[i] = v;
    }
}

// fused: round all four weight matrices in one launch (blockIdx.y selects)
__global__ __launch_bounds__(256) void round4_tf32_kernel(
    const float* __restrict__ w0, const float* __restrict__ w1,
    const float* __restrict__ w2, const float* __restrict__ w3,
    float* __restrict__ o0, float* __restrict__ o1,
    float* __restrict__ o2, float* __restrict__ o3, int n4)
{
    const float* in = (blockIdx.y == 0) ? w0 : (blockIdx.y == 1) ? w1
                    : (blockIdx.y == 2) ? w2 : w3;
    float* out = (blockIdx.y == 0) ? o0 : (blockIdx.y == 1) ? o1
               : (blockIdx.y == 2) ? o2 : o3;
    int i = blockIdx.x * blockDim.x + threadIdx.x;
    if (i < n4) {
        float4 v = ((const float4*)in)[i];
        v.x = __uint_as_float(f2tf(v.x));
        v.y = __uint_as_float(f2tf(v.y));
        v.z = __uint_as_float(f2tf(v.z));
        v.w = __uint_as_float(f2tf(v.w));
        ((float4*)out)[i] = v;
    }
}

// ---------------- TF32 GEMM, 3-stage cp.async, 2 CTAs/SM, ldmatrix A -------
// C = A[MxK] * B[KxN]; A,B pre-rounded to tf32 values in fp32 storage.
// Round-11 best config (128x128 CTA, 8 warps 2x4, each 64x32, 3 stages,
// 2 CTAs/SM) + ldmatrix.x4(b16-view) for A fragments: 1 LDSM replaces 4 LDS.
#define GBM 128
#define GBN 128
#define GBK 32
#define AS_STRIDE 36     // 128x36 floats (144B rows -> LDSM conflict-free)
#define BS_STRIDE 136    // 32x136 floats
#define STAGE_FLOATS (GBM * AS_STRIDE + GBK * BS_STRIDE)   // 8960
#define GEMM_STAGES 3
#define GEMM_SMEM_BYTES (GEMM_STAGES * STAGE_FLOATS * 4)   // 107520
#define GEMM_THREADS 256

__global__ __launch_bounds__(GEMM_THREADS, 2) void tf32_gemm_pipe(
    const float* __restrict__ A, const float* __restrict__ Bm,
    float* __restrict__ Cm, int M, int N, int K)
{
    extern __shared__ float sm[];
    const int tid = threadIdx.x;
    const int bx = blockIdx.x;
    const int by = blockIdx.y;
    const int lane = tid & 31;
    const int wid = tid >> 5;
    const int wm = (wid & 1) * 64;
    const int wn = (wid >> 1) * 32;
    const int g = lane >> 2;
    const int tq = lane & 3;
    // ldmatrix per-thread source row/col within a 16x8-tf32 tile
    const int lm_row = lane & 15;            // 0..15
    const int lm_k4  = (lane >> 4) * 4;      // 0 or 4

    const float* Abase = A + (size_t)by * GBM * K;
    const float* Bbase = Bm + bx * GBN;
    const unsigned sm_sa = (unsigned)__cvta_generic_to_shared(sm);

    float acc[4][4][4];
#pragma unroll
    for (int mt = 0; mt < 4; mt++)
#pragma unroll
        for (int nt = 0; nt < 4; nt++)
#pragma unroll
            for (int i = 0; i < 4; i++) acc[mt][nt][i] = 0.f;

    const int ntiles = K / GBK;

    auto issue = [&](int kt, int st) {
        const unsigned as0 = sm_sa + (unsigned)(st * STAGE_FLOATS) * 4u;
        const unsigned bs0 = as0 + GBM * AS_STRIDE * 4u;
#pragma unroll
        for (int i = 0; i < 4; i++) {
            const int cid = tid + i * GEMM_THREADS;   // 0..1023
            const int r = cid >> 3;                   // 0..127
            const int c = (cid & 7) * 4;              // 0..28
            cp16(as0 + (unsigned)(r * AS_STRIDE + c) * 4u,
                 Abase + (size_t)r * K + kt * GBK + c);
        }
#pragma unroll
        for (int i = 0; i < 4; i++) {
            const int cid = tid + i * GEMM_THREADS;
            const int r = cid >> 5;                   // 0..31
            const int c = (cid & 31) * 4;             // 0..124
            cp16(bs0 + (unsigned)(r * BS_STRIDE + c) * 4u,
                 Bbase + (size_t)(kt * GBK + r) * N + c);
        }
        asm volatile("cp.async.commit_group;\n");
    };

    issue(0, 0);

    for (int kt = 0; kt < ntiles; kt++) {
        if (kt + 1 < ntiles) issue(kt + 1, (kt + 1) % GEMM_STAGES);
        else asm volatile("cp.async.commit_group;\n");
        asm volatile("cp.async.wait_group 1;\n");
        __syncthreads();

        const float* As = sm + (kt % GEMM_STAGES) * STAGE_FLOATS;
        const float* Bs = As + GBM * AS_STRIDE;
        const unsigned as_u = sm_sa + (unsigned)((kt % GEMM_STAGES) * STAGE_FLOATS) * 4u;
        // thread-invariant ldmatrix offset
        const unsigned a_thr = (unsigned)(lm_row * AS_STRIDE + lm_k4) * 4u;

#pragma unroll
        for (int ks = 0; ks < 4; ks++) {
            const int k = ks * 8 + tq;
            unsigned a[4][4], b[4][2];
#pragma unroll
            for (int mt = 0; mt < 4; mt++) {
                const unsigned addr = as_u + a_thr
                    + (unsigned)((wm + mt * 16) * AS_STRIDE) * 4u
                    + (unsigned)(ks * 32);
                ldsm_x4(addr, a[mt]);
            }
#pragma unroll
            for (int nt = 0; nt < 4; nt++) {
                const int n = wn + nt * 8 + g;
                b[nt][0] = __float_as_uint(Bs[k * BS_STRIDE + n]);
                b[nt][1] = __float_as_uint(Bs[(k + 4) * BS_STRIDE + n]);
            }
#pragma unroll
            for (int mt = 0; mt < 4; mt++)
#pragma unroll
                for (int nt = 0; nt < 4; nt++)
                    mma_tf32(acc[mt][nt], a[mt], b[nt]);
        }
        __syncthreads();
    }

#pragma unroll
    for (int mt = 0; mt < 4; mt++) {
        const int r0 = by * GBM + wm + mt * 16 + g;
#pragma unroll
        for (int nt = 0; nt < 4; nt++) {
            const int c0 = bx * GBN + wn + nt * 8 + 2 * tq;
            *(float2*)(Cm + (size_t)r0 * N + c0) = make_float2(acc[mt][nt][0], acc[mt][nt][1]);
            *(float2*)(Cm + (size_t)(r0 + 8) * N + c0) = make_float2(acc[mt][nt][2], acc[mt][nt][3]);
        }
    }
}

// ---------------- gate: v += 2*sigmoid(x[:, :32] @ Wg)[h] * ve -------------
__global__ __launch_bounds__(256) void gate_kernel(
    const float* __restrict__ x, const float* __restrict__ ve,
    const float* __restrict__ Wg, float* __restrict__ v)
{
    const int m = blockIdx.x;
    const int tid = threadIdx.x;
    __shared__ float xg[32];
    __shared__ float g[H_];

    if (tid < 32) xg[tid] = x[(size_t)m * C_ + tid];
    __syncthreads();
    if (tid < H_) {
        float s = 0.f;
#pragma unroll
        for (int i = 0; i < 32; i++) s += xg[i] * Wg[i * H_ + tid];
        g[tid] = 2.f / (1.f + __expf(-s));
    }
    __syncthreads();

    const size_t base = (size_t)m * C_;
    for (int c = tid; c < C_; c += 256) {
        v[base + c] += g[c >> 7] * ve[base + c];
    }
}

// ---------------- RoPE + RMSNorm for q and k (warp per row,head) -----------
__global__ __launch_bounds__(256) void rope_rms_kernel(
    const float* __restrict__ cosT, const float* __restrict__ sinT,
    float* __restrict__ q, float* __restrict__ k)
{
    const int gw = (blockIdx.x * blockDim.x + threadIdx.x) >> 5;
    const int lane = threadIdx.x & 31;
    const int m = gw / H_;
    const int h = gw % H_;
    const int t = m % T_;

    const float c0 = cosT[t * 64 + lane];
    const float c1 = cosT[t * 64 + lane + 32];
    const float s0 = sinT[t * 64 + lane];
    const float s1 = sinT[t * 64 + lane + 32];

#pragma unroll
    for (int a = 0; a < 2; a++) {
        float* ptr = (a == 0 ? q : k) + (size_t)m * C_ + h * D_;
        float f0 = ptr[lane];
        float f1 = ptr[lane + 32];
        float f2 = ptr[lane + 64];
        float f3 = ptr[lane + 96];
        float r0 =  f0 * c0 + f2 * s0;
        float r2 = -f0 * s0 + f2 * c0;
        float r1 =  f1 * c1 + f3 * s1;
        float r3 = -f1 * s1 + f3 * c1;
        float ss = r0*r0 + r1*r1 + r2*r2 + r3*r3;
#pragma unroll
        for (int off = 16; off; off >>= 1) ss += __shfl_xor_sync(0xffffffffu, ss, off);
        float sc = rsqrtf(ss * (1.f / 128.f) + 1e-6f);
        ptr[lane]      = r0 * sc;
        ptr[lane + 32] = r1 * sc;
        ptr[lane + 64] = r2 * sc;
        ptr[lane + 96] = r3 * sc;
    }
}

// ---------------- tensor-core sliding-window attention ---------------------
#define AQ 128
#define ATK 64
#define KS_STRIDE 132
#define VS_STRIDE 136
#define PS_STRIDE 68
#define SMEM_KS_OFF 0
#define SMEM_VS_OFF (ATK * KS_STRIDE)
#define SMEM_PS_OFF (SMEM_VS_OFF + ATK * VS_STRIDE)
#define SMEM_ATTN_FLOATS (SMEM_PS_OFF + AQ * PS_STRIDE)
#define SMEM_ATTN_BYTES (SMEM_ATTN_FLOATS * 4)

__global__ __launch_bounds__(256) void attn_mma_kernel(
    const float* __restrict__ Q, const float* __restrict__ K,
    const float* __restrict__ V, float* __restrict__ O)
{
    extern __shared__ float sm[];
    float* Ks = sm + SMEM_KS_OFF;
    float* Vs = sm + SMEM_VS_OFF;
    float* Ps = sm + SMEM_PS_OFF;

    const int b = blockIdx.z;
    const int h = blockIdx.y;
    const int t0 = blockIdx.x * AQ;
    const int tid = threadIdx.x;
    const int lane = tid & 31;
    const int wid = tid >> 5;
    const int g = lane >> 2;
    const int tq = lane & 3;
    const int wm = wid * 16;

    unsigned qf[16][4];
    {
        const float* qb = Q + ((size_t)(b * T_ + t0 + wm)) * C_ + h * D_;
#pragma unroll
        for (int ks = 0; ks < 16; ks++) {
            const int c0 = ks * 8 + tq;
            qf[ks][0] = f2tf(qb[(size_t)g * C_ + c0] * SCALE_);
            qf[ks][1] = f2tf(qb[(size_t)(g + 8) * C_ + c0] * SCALE_);
            qf[ks][2] = f2tf(qb[(size_t)g * C_ + c0 + 4] * SCALE_);
            qf[ks][3] = f2tf(qb[(size_t)(g + 8) * C_ + c0 + 4] * SCALE_);
        }
    }

    float o[16][4];
#pragma unroll
    for (int nt = 0; nt < 16; nt++)
#pragma unroll
        for (int i = 0; i < 4; i++) o[nt][i] = 0.f;

    float m0 = -1e30f, m1 = -1e30f, l0 = 0.f, l1 = 0.f;
    const int trow0 = t0 + wm + g;
    const int trow1 = trow0 + 8;

    int lo = t0 - W_;
    if (lo < 0) lo = 0;

    for (int ks0 = lo; ks0 < t0 + AQ; ks0 += ATK) {
#pragma unroll
        for (int it = 0; it < 8; it++) {
            const int idx = tid + it * 256;
            const int row = idx >> 5;
            const int c4 = (idx & 31) * 4;
            const size_t gbase = ((size_t)(b * T_ + ks0 + row)) * C_ + h * D_ + c4;
            float4 kv = *(const float4*)(K + gbase);
            float4 vv = *(const float4*)(V + gbase);
            float* kd = Ks + row * KS_STRIDE + c4;
            kd[0] = __uint_as_float(f2tf(kv.x));
            kd[1] = __uint_as_float(f2tf(kv.y));
            kd[2] = __uint_as_float(f2tf(kv.z));
            kd[3] = __uint_as_float(f2tf(kv.w));
            float* vd = Vs + row * VS_STRIDE + c4;
            vd[0] = __uint_as_float(f2tf(vv.x));
            vd[1] = __uint_as_float(f2tf(vv.y));
            vd[2] = __uint_as_float(f2tf(vv.z));
            vd[3] = __uint_as_float(f2tf(vv.w));
        }
        __syncthreads();

        float s[8][4];
#pragma unroll
        for (int nt = 0; nt < 8; nt++)
#pragma unroll
            for (int i = 0; i < 4; i++) s[nt][i] = 0.f;

#pragma unroll
        for (int ksp = 0; ksp < 16; ksp++) {
            const int k = ksp * 8 + tq;
            unsigned bfr[8][2];
#pragma unroll
            for (int nt = 0; nt < 8; nt++) {
                const int n = nt * 8 + g;
                bfr[nt][0] = __float_as_uint(Ks[n * KS_STRIDE + k]);
                bfr[nt][1] = __float_as_uint(Ks[n * KS_STRIDE + k + 4]);
            }
#pragma unroll
            for (int nt = 0; nt < 8; nt++)
                mma_tf32(s[nt], qf[ksp], bfr[nt]);
        }

        float mt0 = -1e30f, mt1 = -1e30f;
#pragma unroll
        for (int nt = 0; nt < 8; nt++) {
            const int kt0 = ks0 + nt * 8 + 2 * tq;
            const int kt1 = kt0 + 1;
            s[nt][0] = (kt0 <= trow0 && kt0 >= trow0 - W_) ? s[nt][0] : -1e30f;
            s[nt][1] = (kt1 <= trow0 && kt1 >= trow0 - W_) ? s[nt][1] : -1e30f;
            s[nt][2] = (kt0 <= trow1 && kt0 >= trow1 - W_) ? s[nt][2] : -1e30f;
            s[nt][3] = (kt1 <= trow1 && kt1 >= trow1 - W_) ? s[nt][3] : -1e30f;
            mt0 = fmaxf(mt0, fmaxf(s[nt][0], s[nt][1]));
            mt1 = fmaxf(mt1, fmaxf(s[nt][2], s[nt][3]));
        }
        mt0 = fmaxf(mt0, __shfl_xor_sync(0xffffffffu, mt0, 1));
        mt0 = fmaxf(mt0, __shfl_xor_sync(0xffffffffu, mt0, 2));
        mt1 = fmaxf(mt1, __shfl_xor_sync(0xffffffffu, mt1, 1));
        mt1 = fmaxf(mt1, __shfl_xor_sync(0xffffffffu, mt1, 2));

        const float mn0 = fmaxf(m0, mt0);
        const float mn1 = fmaxf(m1, mt1);
        const float corr0 = __expf(m0 - mn0);
        const float corr1 = __expf(m1 - mn1);
        m0 = mn0; m1 = mn1;

        float ls0 = 0.f, ls1 = 0.f;
        float* pw0 = Ps + (wm + g) * PS_STRIDE;
        float* pw1 = Ps + (wm + g + 8) * PS_STRIDE;
#pragma unroll
        for (int nt = 0; nt < 8; nt++) {
            const int c = nt * 8 + 2 * tq;
            float p00 = (s[nt][0] > -1e29f) ? __expf(s[nt][0] - mn0) : 0.f;
            float p01 = (s[nt][1] > -1e29f) ? __expf(s[nt][1] - mn0) : 0.f;
            float p10 = (s[nt][2] > -1e29f) ? __expf(s[nt][2] - mn1) : 0.f;
            float p11 = (s[nt][3] > -1e29f) ? __expf(s[nt][3] - mn1) : 0.f;
            ls0 += p00 + p01;
            ls1 += p10 + p11;
            pw0[c]     = __uint_as_float(f2tf(p00));
            pw0[c + 1] = __uint_as_float(f2tf(p01));
            pw1[c]     = __uint_as_float(f2tf(p10));
            pw1[c + 1] = __uint_as_float(f2tf(p11));
        }
        ls0 += __shfl_xor_sync(0xffffffffu, ls0, 1);
        ls0 += __shfl_xor_sync(0xffffffffu, ls0, 2);
        ls1 += __shfl_xor_sync(0xffffffffu, ls1, 1);
        ls1 += __shfl_xor_sync(0xffffffffu, ls1, 2);
        l0 = l0 * corr0 + ls0;
        l1 = l1 * corr1 + ls1;

#pragma unroll
        for (int nt = 0; nt < 16; nt++) {
            o[nt][0] *= corr0; o[nt][1] *= corr0;
            o[nt][2] *= corr1; o[nt][3] *= corr1;
        }

        __syncwarp();

#pragma unroll
        for (int ksp = 0; ksp < 8; ksp++) {
            const int k = ksp * 8 + tq;
            unsigned a[4];
            a[0] = __float_as_uint(Ps[(wm + g) * PS_STRIDE + k]);
            a[1] = __float_as_uint(Ps[(wm + g + 8) * PS_STRIDE + k]);
            a[2] = __float_as_uint(Ps[(wm + g) * PS_STRIDE + k + 4]);
            a[3] = __float_as_uint(Ps[(wm + g + 8) * PS_STRIDE + k + 4]);
            unsigned bfr[2];
#pragma unroll
            for (int nt = 0; nt < 16; nt++) {
                const int n = nt * 8 + g;
                bfr[0] = __float_as_uint(Vs[k * VS_STRIDE + n]);
                bfr[1] = __float_as_uint(Vs[(k + 4) * VS_STRIDE + n]);
                mma_tf32(o[nt], a, bfr);
            }
        }
        __syncthreads();
    }

    // epilogue: write tf32-rounded output (proj GEMM reads it raw)
    const float inv0 = 1.f / l0;
    const float inv1 = 1.f / l1;
    float* ob0 = O + ((size_t)(b * T_ + trow0)) * C_ + h * D_;
    float* ob1 = O + ((size_t)(b * T_ + trow1)) * C_ + h * D_;
#pragma unroll
    for (int nt = 0; nt < 16; nt++) {
        const int c = nt * 8 + 2 * tq;
        *(float2*)(ob0 + c) = make_float2(__uint_as_float(f2tf(o[nt][0] * inv0)),
                                          __uint_as_float(f2tf(o[nt][1] * inv0)));
        *(float2*)(ob1 + c) = make_float2(__uint_as_float(f2tf(o[nt][2] * inv1)),
                                          __uint_as_float(f2tf(o[nt][3] * inv1)));
    }
}

// ---------------- launch ---------------------------------------------------
extern "C" void kernel_launch(void* const* d_in, const int* in_sizes, int n_in,
                              void* d_out, int out_size)
{
    const float* x     = (const float*)d_in[0];
    const float* ve    = (const float*)d_in[1];
    const float* cosT  = (const float*)d_in[2];
    const float* sinT  = (const float*)d_in[3];
    const float* Wq    = (const float*)d_in[4];
    const float* Wk    = (const float*)d_in[5];
    const float* Wv    = (const float*)d_in[6];
    const float* Wproj = (const float*)d_in[7];
    const float* Wg    = (const float*)d_in[8];
    float* out = (float*)d_out;

    float *q, *k, *v, *o, *xt, *wq, *wk, *wv, *wp;
    cudaGetSymbolAddress((void**)&q, g_q);
    cudaGetSymbolAddress((void**)&k, g_k);
    cudaGetSymbolAddress((void**)&v, g_v);
    cudaGetSymbolAddress((void**)&o, g_o);
    cudaGetSymbolAddress((void**)&xt, g_xt);
    cudaGetSymbolAddress((void**)&wq, g_wq);
    cudaGetSymbolAddress((void**)&wk, g_wk);
    cudaGetSymbolAddress((void**)&wv, g_wv);
    cudaGetSymbolAddress((void**)&wp, g_wp);

    static int attr_set = 0;
    if (!attr_set) {
        cudaFuncSetAttribute(attn_mma_kernel,
                             cudaFuncAttributeMaxDynamicSharedMemorySize,
                             SMEM_ATTN_BYTES);
        cudaFuncSetAttribute(tf32_gemm_pipe,
                             cudaFuncAttributeMaxDynamicSharedMemorySize,
                             GEMM_SMEM_BYTES);
        attr_set = 1;
    }

    // launch 0: round x; launch 1: round all weights (fused)
    const int nx4 = (M_ * C_) / 4;
    const int nw4 = (C_ * C_) / 4;
    round_tf32_kernel<<<nx4 / 256, 256>>>(x, xt, nx4);
    dim3 wgrid(nw4 / 256, 4);
    round4_tf32_kernel<<<wgrid, 256>>>(Wq, Wk, Wv, Wproj, wq, wk, wv, wp, nw4);

    // launches 2,3,4: QKV GEMMs (ncu -s5 capture lands here)
    dim3 gemm_grid(C_ / GBN, M_ / GBM);
    tf32_gemm_pipe<<<gemm_grid, GEMM_THREADS, GEMM_SMEM_BYTES>>>(xt, wq, q, M_, C_, C_);
    tf32_gemm_pipe<<<gemm_grid, GEMM_THREADS, GEMM_SMEM_BYTES>>>(xt, wk, k, M_, C_, C_);
    tf32_gemm_pipe<<<gemm_grid, GEMM_THREADS, GEMM_SMEM_BYTES>>>(xt, wv, v, M_, C_, C_);

    gate_kernel<<<M_, 256>>>(x, ve, Wg, v);
    rope_rms_kernel<<<(M_ * H_) / 8, 256>>>(cosT, sinT, q, k);

    dim3 attn_grid(T_ / AQ, H_, B_);
    attn_mma_kernel<<<attn_grid, 256, SMEM_ATTN_BYTES>>>(q, k, v, o);

    tf32_gemm_pipe<<<gemm_grid, GEMM_THREADS, GEMM_SMEM_BYTES>>>(o, wp, out, M_, C_, C_);
}

// round 16
// speedup vs baseline: 1.3054x; 1.1380x over previous
#include <cuda_runtime.h>
#include <cuda_bf16.h>
#include <math.h>
#include <stdint.h>

// Problem constants
#define B_ 2
#define T_ 4096
#define C_ 2048
#define H_ 16
#define D_ 128
#define W_ 1024
#define M_ (B_*T_)          // 8192 rows
#define SCALE_ (0.08838834764831845f)   // 1/sqrt(128)

// ---------------- scratch (device globals; no cudaMalloc allowed) ----------
__device__ float g_q[(size_t)M_ * C_];
__device__ float g_k[(size_t)M_ * C_];
__device__ float g_v[(size_t)M_ * C_];
__device__ float g_o[(size_t)M_ * C_];
__device__ float g_xt[(size_t)M_ * C_];       // tf32-rounded x
__device__ float g_wq[(size_t)C_ * C_];
__device__ float g_wk[(size_t)C_ * C_];
__device__ float g_wv[(size_t)C_ * C_];
__device__ float g_wp[(size_t)C_ * C_];

// ---------------- common helpers -------------------------------------------
__device__ __forceinline__ unsigned f2tf(float f) {
    unsigned u;
    asm("cvt.rna.tf32.f32 %0, %1;" : "=r"(u) : "f"(f));
    return u;
}

__device__ __forceinline__ void mma_tf32(float* c, const unsigned* a, const unsigned* b) {
    asm volatile(
        "mma.sync.aligned.m16n8k8.row.col.f32.tf32.tf32.f32 "
        "{%0,%1,%2,%3}, {%4,%5,%6,%7}, {%8,%9}, {%0,%1,%2,%3};"
        : "+f"(c[0]), "+f"(c[1]), "+f"(c[2]), "+f"(c[3])
        : "r"(a[0]), "r"(a[1]), "r"(a[2]), "r"(a[3]), "r"(b[0]), "r"(b[1]));
}

__device__ __forceinline__ void cp16(unsigned s_addr, const float* g) {
    asm volatile("cp.async.cg.shared.global [%0], [%1], 16;\n" :: "r"(s_addr), "l"(g));
}

// ldmatrix x4 (b16 view) -> exactly the tf32 m16n8k8 A fragment
__device__ __forceinline__ void ldsm_x4(unsigned addr, unsigned* r) {
    asm volatile(
        "ldmatrix.sync.aligned.m8n8.x4.shared.b16 {%0,%1,%2,%3}, [%4];"
        : "=r"(r[0]), "=r"(r[1]), "=r"(r[2]), "=r"(r[3]) : "r"(addr));
}

// ---------------- tf32 rounding pre-passes ----------------------------------
__global__ __launch_bounds__(256) void round_tf32_kernel(
    const float* __restrict__ in, float* __restrict__ out, int n4)
{
    int i = blockIdx.x * blockDim.x + threadIdx.x;
    if (i < n4) {
        float4 v = ((const float4*)in)[i];
        v.x = __uint_as_float(f2tf(v.x));
        v.y = __uint_as_float(f2tf(v.y));
        v.z = __uint_as_float(f2tf(v.z));
        v.w = __uint_as_float(f2tf(v.w));
        ((float4*)out)[i] = v;
    }
}

__global__ __launch_bounds__(256) void round4_tf32_kernel(
    const float* __restrict__ w0, const float* __restrict__ w1,
    const float* __restrict__ w2, const float* __restrict__ w3,
    float* __restrict__ o0, float* __restrict__ o1,
    float* __restrict__ o2, float* __restrict__ o3, int n4)
{
    const float* in = (blockIdx.y == 0) ? w0 : (blockIdx.y == 1) ? w1
                    : (blockIdx.y == 2) ? w2 : w3;
    float* out = (blockIdx.y == 0) ? o0 : (blockIdx.y == 1) ? o1
               : (blockIdx.y == 2) ? o2 : o3;
    int i = blockIdx.x * blockDim.x + threadIdx.x;
    if (i < n4) {
        float4 v = ((const float4*)in)[i];
        v.x = __uint_as_float(f2tf(v.x));
        v.y = __uint_as_float(f2tf(v.y));
        v.z = __uint_as_float(f2tf(v.z));
        v.w = __uint_as_float(f2tf(v.w));
        ((float4*)out)[i] = v;
    }
}

// ---------------- GEMM tile configuration ----------------------------------
#define GBM 128
#define GBN 128
#define GBK 32
#define AS_STRIDE 36     // 128x36 floats (144B rows -> LDSM conflict-free)
#define BS_STRIDE 136    // 32x136 floats
#define STAGE_FLOATS (GBM * AS_STRIDE + GBK * BS_STRIDE)   // 8960
#define GEMM_STAGES 3
#define GEMM_SMEM_BYTES (GEMM_STAGES * STAGE_FLOATS * 4)   // 107520
#define GEMM_THREADS 256

// Shared GEMM mainloop: A(row-major MxK) x B(row-major KxN tiles), 3-stage
// cp.async, ONE barrier per iteration: issue(j+1) at iter j writes stage
// (j+1)%3 = (j-2)%3, last read by compute(j-2); every thread passed iter
// j-1's barrier which post-dates compute(j-2) -> no WAR race.
#define GEMM_MAINLOOP(Abase, Bbase, Kdim)                                      \
    const unsigned sm_sa = (unsigned)__cvta_generic_to_shared(sm);             \
    float acc[4][4][4];                                                        \
    _Pragma("unroll")                                                          \
    for (int mt = 0; mt < 4; mt++)                                             \
        _Pragma("unroll")                                                      \
        for (int nt = 0; nt < 4; nt++)                                         \
            _Pragma("unroll")                                                  \
            for (int i = 0; i < 4; i++) acc[mt][nt][i] = 0.f;                  \
    const int ntiles = (Kdim) / GBK;                                           \
    auto issue = [&](int kt, int st) {                                         \
        const unsigned as0 = sm_sa + (unsigned)(st * STAGE_FLOATS) * 4u;       \
        const unsigned bs0 = as0 + GBM * AS_STRIDE * 4u;                       \
        _Pragma("unroll")                                                      \
        for (int i = 0; i < 4; i++) {                                          \
            const int cid = tid + i * GEMM_THREADS;                            \
            const int r = cid >> 3;                                            \
            const int c = (cid & 7) * 4;                                       \
            cp16(as0 + (unsigned)(r * AS_STRIDE + c) * 4u,                     \
                 (Abase) + (size_t)r * (Kdim) + kt * GBK + c);                 \
        }                                                                      \
        _Pragma("unroll")                                                      \
        for (int i = 0; i < 4; i++) {                                          \
            const int cid = tid + i * GEMM_THREADS;                            \
            const int r = cid >> 5;                                            \
            const int c = (cid & 31) * 4;                                      \
            cp16(bs0 + (unsigned)(r * BS_STRIDE + c) * 4u,                     \
                 (Bbase) + (size_t)(kt * GBK + r) * C_ + c);                   \
        }                                                                      \
        asm volatile("cp.async.commit_group;\n");                              \
    };                                                                         \
    issue(0, 0);                                                               \
    for (int kt = 0; kt < ntiles; kt++) {                                      \
        if (kt + 1 < ntiles) issue(kt + 1, (kt + 1) % GEMM_STAGES);            \
        else asm volatile("cp.async.commit_group;\n");                         \
        asm volatile("cp.async.wait_group 1;\n");                              \
        __syncthreads();                                                       \
        const float* Bs = sm + (kt % GEMM_STAGES) * STAGE_FLOATS               \
                          + GBM * AS_STRIDE;                                   \
        const unsigned as_u = sm_sa                                            \
            + (unsigned)((kt % GEMM_STAGES) * STAGE_FLOATS) * 4u;              \
        const unsigned a_thr = (unsigned)(lm_row * AS_STRIDE + lm_k4) * 4u;    \
        _Pragma("unroll")                                                      \
        for (int ks = 0; ks < 4; ks++) {                                       \
            const int k = ks * 8 + tq;                                         \
            unsigned a[4][4], b[4][2];                                         \
            _Pragma("unroll")                                                  \
            for (int mt = 0; mt < 4; mt++) {                                   \
                const unsigned addr = as_u + a_thr                             \
                    + (unsigned)((wm + mt * 16) * AS_STRIDE) * 4u              \
                    + (unsigned)(ks * 32);                                     \
                ldsm_x4(addr, a[mt]);                                          \
            }                                                                  \
            _Pragma("unroll")                                                  \
            for (int nt = 0; nt < 4; nt++) {                                   \
                const int n = wn + nt * 8 + g;                                 \
                b[nt][0] = __float_as_uint(Bs[k * BS_STRIDE + n]);             \
                b[nt][1] = __float_as_uint(Bs[(k + 4) * BS_STRIDE + n]);       \
            }                                                                  \
            _Pragma("unroll")                                                  \
            for (int mt = 0; mt < 4; mt++)                                     \
                _Pragma("unroll")                                              \
                for (int nt = 0; nt < 4; nt++)                                 \
                    mma_tf32(acc[mt][nt], a[mt], b[nt]);                       \
        }                                                                      \
    }

// ---------------- fused QKV GEMM (z selects weight/output; z==2 gates) -----
__global__ __launch_bounds__(GEMM_THREADS, 2) void qkv_gemm_fused(
    const float* __restrict__ A,
    const float* __restrict__ Wq, const float* __restrict__ Wk,
    const float* __restrict__ Wv,
    float* __restrict__ Q, float* __restrict__ Ko, float* __restrict__ V,
    const float* __restrict__ xraw, const float* __restrict__ ve,
    const float* __restrict__ Wg)
{
    extern __shared__ float sm[];
    const int tid = threadIdx.x;
    const int bx = blockIdx.x;
    const int by = blockIdx.y;
    const int z = blockIdx.z;
    const int lane = tid & 31;
    const int wid = tid >> 5;
    const int wm = (wid & 1) * 64;
    const int wn = (wid >> 1) * 32;
    const int g = lane >> 2;
    const int tq = lane & 3;
    const int lm_row = lane & 15;
    const int lm_k4  = (lane >> 4) * 4;

    const float* Bm = (z == 0) ? Wq : (z == 1) ? Wk : Wv;
    float* Cm = (z == 0) ? Q : (z == 1) ? Ko : V;
    const float* Abase = A + (size_t)by * GBM * C_;
    const float* Bbase = Bm + bx * GBN;

    GEMM_MAINLOOP(Abase, Bbase, C_)

    if (z == 2) {
        // gate: head for this CTA tile is exactly bx (GBN == D)
        __syncthreads();   // all warps done reading pipeline smem
        if (tid < GBM) {
            const float* xr = xraw + (size_t)(by * GBM + tid) * C_;
            float ds = 0.f;
#pragma unroll
            for (int i = 0; i < 32; i++) ds += xr[i] * Wg[i * H_ + bx];
            sm[tid] = 2.f / (1.f + __expf(-ds));
        }
        __syncthreads();
#pragma unroll
        for (int mt = 0; mt < 4; mt++) {
            const int lr0 = wm + mt * 16 + g;
            const float g0 = sm[lr0];
            const float g1 = sm[lr0 + 8];
            const int r0 = by * GBM + lr0;
#pragma unroll
            for (int nt = 0; nt < 4; nt++) {
                const int c0 = bx * GBN + wn + nt * 8 + 2 * tq;
                float2 v0 = *(const float2*)(ve + (size_t)r0 * C_ + c0);
                float2 v1 = *(const float2*)(ve + (size_t)(r0 + 8) * C_ + c0);
                *(float2*)(Cm + (size_t)r0 * C_ + c0) =
                    make_float2(acc[mt][nt][0] + g0 * v0.x,
                                acc[mt][nt][1] + g0 * v0.y);
                *(float2*)(Cm + (size_t)(r0 + 8) * C_ + c0) =
                    make_float2(acc[mt][nt][2] + g1 * v1.x,
                                acc[mt][nt][3] + g1 * v1.y);
            }
        }
    } else {
#pragma unroll
        for (int mt = 0; mt < 4; mt++) {
            const int r0 = by * GBM + wm + mt * 16 + g;
#pragma unroll
            for (int nt = 0; nt < 4; nt++) {
                const int c0 = bx * GBN + wn + nt * 8 + 2 * tq;
                *(float2*)(Cm + (size_t)r0 * C_ + c0) =
                    make_float2(acc[mt][nt][0], acc[mt][nt][1]);
                *(float2*)(Cm + (size_t)(r0 + 8) * C_ + c0) =
                    make_float2(acc[mt][nt][2], acc[mt][nt][3]);
            }
        }
    }
}

// ---------------- plain GEMM (output projection) ---------------------------
__global__ __launch_bounds__(GEMM_THREADS, 2) void tf32_gemm_pipe(
    const float* __restrict__ A, const float* __restrict__ Bm,
    float* __restrict__ Cm)
{
    extern __shared__ float sm[];
    const int tid = threadIdx.x;
    const int bx = blockIdx.x;
    const int by = blockIdx.y;
    const int lane = tid & 31;
    const int wid = tid >> 5;
    const int wm = (wid & 1) * 64;
    const int wn = (wid >> 1) * 32;
    const int g = lane >> 2;
    const int tq = lane & 3;
    const int lm_row = lane & 15;
    const int lm_k4  = (lane >> 4) * 4;

    const float* Abase = A + (size_t)by * GBM * C_;
    const float* Bbase = Bm + bx * GBN;

    GEMM_MAINLOOP(Abase, Bbase, C_)

#pragma unroll
    for (int mt = 0; mt < 4; mt++) {
        const int r0 = by * GBM + wm + mt * 16 + g;
#pragma unroll
        for (int nt = 0; nt < 4; nt++) {
            const int c0 = bx * GBN + wn + nt * 8 + 2 * tq;
            *(float2*)(Cm + (size_t)r0 * C_ + c0) =
                make_float2(acc[mt][nt][0], acc[mt][nt][1]);
            *(float2*)(Cm + (size_t)(r0 + 8) * C_ + c0) =
                make_float2(acc[mt][nt][2], acc[mt][nt][3]);
        }
    }
}

// ---------------- RoPE + RMSNorm for q and k (warp per row,head) -----------
__global__ __launch_bounds__(256) void rope_rms_kernel(
    const float* __restrict__ cosT, const float* __restrict__ sinT,
    float* __restrict__ q, float* __restrict__ k)
{
    const int gw = (blockIdx.x * blockDim.x + threadIdx.x) >> 5;
    const int lane = threadIdx.x & 31;
    const int m = gw / H_;
    const int h = gw % H_;
    const int t = m % T_;

    const float c0 = cosT[t * 64 + lane];
    const float c1 = cosT[t * 64 + lane + 32];
    const float s0 = sinT[t * 64 + lane];
    const float s1 = sinT[t * 64 + lane + 32];

#pragma unroll
    for (int a = 0; a < 2; a++) {
        float* ptr = (a == 0 ? q : k) + (size_t)m * C_ + h * D_;
        float f0 = ptr[lane];
        float f1 = ptr[lane + 32];
        float f2 = ptr[lane + 64];
        float f3 = ptr[lane + 96];
        float r0 =  f0 * c0 + f2 * s0;
        float r2 = -f0 * s0 + f2 * c0;
        float r1 =  f1 * c1 + f3 * s1;
        float r3 = -f1 * s1 + f3 * c1;
        float ss = r0*r0 + r1*r1 + r2*r2 + r3*r3;
#pragma unroll
        for (int off = 16; off; off >>= 1) ss += __shfl_xor_sync(0xffffffffu, ss, off);
        float sc = rsqrtf(ss * (1.f / 128.f) + 1e-6f);
        ptr[lane]      = r0 * sc;
        ptr[lane + 32] = r1 * sc;
        ptr[lane + 64] = r2 * sc;
        ptr[lane + 96] = r3 * sc;
    }
}

// ---------------- tensor-core sliding-window attention ---------------------
#define AQ 128
#define ATK 64
#define KS_STRIDE 132
#define VS_STRIDE 136
#define PS_STRIDE 68
#define SMEM_KS_OFF 0
#define SMEM_VS_OFF (ATK * KS_STRIDE)
#define SMEM_PS_OFF (SMEM_VS_OFF + ATK * VS_STRIDE)
#define SMEM_ATTN_FLOATS (SMEM_PS_OFF + AQ * PS_STRIDE)
#define SMEM_ATTN_BYTES (SMEM_ATTN_FLOATS * 4)

__global__ __launch_bounds__(256) void attn_mma_kernel(
    const float* __restrict__ Q, const float* __restrict__ K,
    const float* __restrict__ V, float* __restrict__ O)
{
    extern __shared__ float sm[];
    float* Ks = sm + SMEM_KS_OFF;
    float* Vs = sm + SMEM_VS_OFF;
    float* Ps = sm + SMEM_PS_OFF;

    const int b = blockIdx.z;
    const int h = blockIdx.y;
    const int t0 = blockIdx.x * AQ;
    const int tid = threadIdx.x;
    const int lane = tid & 31;
    const int wid = tid >> 5;
    const int g = lane >> 2;
    const int tq = lane & 3;
    const int wm = wid * 16;

    unsigned qf[16][4];
    {
        const float* qb = Q + ((size_t)(b * T_ + t0 + wm)) * C_ + h * D_;
#pragma unroll
        for (int ks = 0; ks < 16; ks++) {
            const int c0 = ks * 8 + tq;
            qf[ks][0] = f2tf(qb[(size_t)g * C_ + c0] * SCALE_);
            qf[ks][1] = f2tf(qb[(size_t)(g + 8) * C_ + c0] * SCALE_);
            qf[ks][2] = f2tf(qb[(size_t)g * C_ + c0 + 4] * SCALE_);
            qf[ks][3] = f2tf(qb[(size_t)(g + 8) * C_ + c0 + 4] * SCALE_);
        }
    }

    float o[16][4];
#pragma unroll
    for (int nt = 0; nt < 16; nt++)
#pragma unroll
        for (int i = 0; i < 4; i++) o[nt][i] = 0.f;

    float m0 = -1e30f, m1 = -1e30f, l0 = 0.f, l1 = 0.f;
    const int trow0 = t0 + wm + g;
    const int trow1 = trow0 + 8;

    int lo = t0 - W_;
    if (lo < 0) lo = 0;

    for (int ks0 = lo; ks0 < t0 + AQ; ks0 += ATK) {
#pragma unroll
        for (int it = 0; it < 8; it++) {
            const int idx = tid + it * 256;
            const int row = idx >> 5;
            const int c4 = (idx & 31) * 4;
            const size_t gbase = ((size_t)(b * T_ + ks0 + row)) * C_ + h * D_ + c4;
            float4 kv = *(const float4*)(K + gbase);
            float4 vv = *(const float4*)(V + gbase);
            float* kd = Ks + row * KS_STRIDE + c4;
            kd[0] = __uint_as_float(f2tf(kv.x));
            kd[1] = __uint_as_float(f2tf(kv.y));
            kd[2] = __uint_as_float(f2tf(kv.z));
            kd[3] = __uint_as_float(f2tf(kv.w));
            float* vd = Vs + row * VS_STRIDE + c4;
            vd[0] = __uint_as_float(f2tf(vv.x));
            vd[1] = __uint_as_float(f2tf(vv.y));
            vd[2] = __uint_as_float(f2tf(vv.z));
            vd[3] = __uint_as_float(f2tf(vv.w));
        }
        __syncthreads();

        float s[8][4];
#pragma unroll
        for (int nt = 0; nt < 8; nt++)
#pragma unroll
            for (int i = 0; i < 4; i++) s[nt][i] = 0.f;

#pragma unroll
        for (int ksp = 0; ksp < 16; ksp++) {
            const int k = ksp * 8 + tq;
            unsigned bfr[8][2];
#pragma unroll
            for (int nt = 0; nt < 8; nt++) {
                const int n = nt * 8 + g;
                bfr[nt][0] = __float_as_uint(Ks[n * KS_STRIDE + k]);
                bfr[nt][1] = __float_as_uint(Ks[n * KS_STRIDE + k + 4]);
            }
#pragma unroll
            for (int nt = 0; nt < 8; nt++)
                mma_tf32(s[nt], qf[ksp], bfr[nt]);
        }

        float mt0 = -1e30f, mt1 = -1e30f;
#pragma unroll
        for (int nt = 0; nt < 8; nt++) {
            const int kt0 = ks0 + nt * 8 + 2 * tq;
            const int kt1 = kt0 + 1;
            s[nt][0] = (kt0 <= trow0 && kt0 >= trow0 - W_) ? s[nt][0] : -1e30f;
            s[nt][1] = (kt1 <= trow0 && kt1 >= trow0 - W_) ? s[nt][1] : -1e30f;
            s[nt][2] = (kt0 <= trow1 && kt0 >= trow1 - W_) ? s[nt][2] : -1e30f;
            s[nt][3] = (kt1 <= trow1 && kt1 >= trow1 - W_) ? s[nt][3] : -1e30f;
            mt0 = fmaxf(mt0, fmaxf(s[nt][0], s[nt][1]));
            mt1 = fmaxf(mt1, fmaxf(s[nt][2], s[nt][3]));
        }
        mt0 = fmaxf(mt0, __shfl_xor_sync(0xffffffffu, mt0, 1));
        mt0 = fmaxf(mt0, __shfl_xor_sync(0xffffffffu, mt0, 2));
        mt1 = fmaxf(mt1, __shfl_xor_sync(0xffffffffu, mt1, 1));
        mt1 = fmaxf(mt1, __shfl_xor_sync(0xffffffffu, mt1, 2));

        const float mn0 = fmaxf(m0, mt0);
        const float mn1 = fmaxf(m1, mt1);
        const float corr0 = __expf(m0 - mn0);
        const float corr1 = __expf(m1 - mn1);
        m0 = mn0; m1 = mn1;

        float ls0 = 0.f, ls1 = 0.f;
        float* pw0 = Ps + (wm + g) * PS_STRIDE;
        float* pw1 = Ps + (wm + g + 8) * PS_STRIDE;
#pragma unroll
        for (int nt = 0; nt < 8; nt++) {
            const int c = nt * 8 + 2 * tq;
            float p00 = (s[nt][0] > -1e29f) ? __expf(s[nt][0] - mn0) : 0.f;
            float p01 = (s[nt][1] > -1e29f) ? __expf(s[nt][1] - mn0) : 0.f;
            float p10 = (s[nt][2] > -1e29f) ? __expf(s[nt][2] - mn1) : 0.f;
            float p11 = (s[nt][3] > -1e29f) ? __expf(s[nt][3] - mn1) : 0.f;
            ls0 += p00 + p01;
            ls1 += p10 + p11;
            pw0[c]     = __uint_as_float(f2tf(p00));
            pw0[c + 1] = __uint_as_float(f2tf(p01));
            pw1[c]     = __uint_as_float(f2tf(p10));
            pw1[c + 1] = __uint_as_float(f2tf(p11));
        }
        ls0 += __shfl_xor_sync(0xffffffffu, ls0, 1);
        ls0 += __shfl_xor_sync(0xffffffffu, ls0, 2);
        ls1 += __shfl_xor_sync(0xffffffffu, ls1, 1);
        ls1 += __shfl_xor_sync(0xffffffffu, ls1, 2);
        l0 = l0 * corr0 + ls0;
        l1 = l1 * corr1 + ls1;

#pragma unroll
        for (int nt = 0; nt < 16; nt++) {
            o[nt][0] *= corr0; o[nt][1] *= corr0;
            o[nt][2] *= corr1; o[nt][3] *= corr1;
        }

        __syncwarp();

#pragma unroll
        for (int ksp = 0; ksp < 8; ksp++) {
            const int k = ksp * 8 + tq;
            unsigned a[4];
            a[0] = __float_as_uint(Ps[(wm + g) * PS_STRIDE + k]);
            a[1] = __float_as_uint(Ps[(wm + g + 8) * PS_STRIDE + k]);
            a[2] = __float_as_uint(Ps[(wm + g) * PS_STRIDE + k + 4]);
            a[3] = __float_as_uint(Ps[(wm + g + 8) * PS_STRIDE + k + 4]);
            unsigned bfr[2];
#pragma unroll
            for (int nt = 0; nt < 16; nt++) {
                const int n = nt * 8 + g;
                bfr[0] = __float_as_uint(Vs[k * VS_STRIDE + n]);
                bfr[1] = __float_as_uint(Vs[(k + 4) * VS_STRIDE + n]);
                mma_tf32(o[nt], a, bfr);
            }
        }
        __syncthreads();
    }

    // epilogue: write tf32-rounded output (proj GEMM reads it raw)
    const float inv0 = 1.f / l0;
    const float inv1 = 1.f / l1;
    float* ob0 = O + ((size_t)(b * T_ + trow0)) * C_ + h * D_;
    float* ob1 = O + ((size_t)(b * T_ + trow1)) * C_ + h * D_;
#pragma unroll
    for (int nt = 0; nt < 16; nt++) {
        const int c = nt * 8 + 2 * tq;
        *(float2*)(ob0 + c) = make_float2(__uint_as_float(f2tf(o[nt][0] * inv0)),
                                          __uint_as_float(f2tf(o[nt][1] * inv0)));
        *(float2*)(ob1 + c) = make_float2(__uint_as_float(f2tf(o[nt][2] * inv1)),
                                          __uint_as_float(f2tf(o[nt][3] * inv1)));
    }
}

// ---------------- launch ---------------------------------------------------
extern "C" void kernel_launch(void* const* d_in, const int* in_sizes, int n_in,
                              void* d_out, int out_size)
{
    const float* x     = (const float*)d_in[0];
    const float* ve    = (const float*)d_in[1];
    const float* cosT  = (const float*)d_in[2];
    const float* sinT  = (const float*)d_in[3];
    const float* Wq    = (const float*)d_in[4];
    const float* Wk    = (const float*)d_in[5];
    const float* Wv    = (const float*)d_in[6];
    const float* Wproj = (const float*)d_in[7];
    const float* Wg    = (const float*)d_in[8];
    float* out = (float*)d_out;

    float *q, *k, *v, *o, *xt, *wq, *wk, *wv, *wp;
    cudaGetSymbolAddress((void**)&q, g_q);
    cudaGetSymbolAddress((void**)&k, g_k);
    cudaGetSymbolAddress((void**)&v, g_v);
    cudaGetSymbolAddress((void**)&o, g_o);
    cudaGetSymbolAddress((void**)&xt, g_xt);
    cudaGetSymbolAddress((void**)&wq, g_wq);
    cudaGetSymbolAddress((void**)&wk, g_wk);
    cudaGetSymbolAddress((void**)&wv, g_wv);
    cudaGetSymbolAddress((void**)&wp, g_wp);

    static int attr_set = 0;
    if (!attr_set) {
        cudaFuncSetAttribute(attn_mma_kernel,
                             cudaFuncAttributeMaxDynamicSharedMemorySize,
                             SMEM_ATTN_BYTES);
        cudaFuncSetAttribute(tf32_gemm_pipe,
                             cudaFuncAttributeMaxDynamicSharedMemorySize,
                             GEMM_SMEM_BYTES);
        cudaFuncSetAttribute(qkv_gemm_fused,
                             cudaFuncAttributeMaxDynamicSharedMemorySize,
                             GEMM_SMEM_BYTES);
        attr_set = 1;
    }

    const int nx4 = (M_ * C_) / 4;
    const int nw4 = (C_ * C_) / 4;
    round_tf32_kernel<<<nx4 / 256, 256>>>(x, xt, nx4);
    dim3 wgrid(nw4 / 256, 4);
    round4_tf32_kernel<<<wgrid, 256>>>(Wq, Wk, Wv, Wproj, wq, wk, wv, wp, nw4);

    // fused QKV projections + gated ve add (z==2)
    dim3 qkv_grid(C_ / GBN, M_ / GBM, 3);
    qkv_gemm_fused<<<qkv_grid, GEMM_THREADS, GEMM_SMEM_BYTES>>>(
        xt, wq, wk, wv, q, k, v, x, ve, Wg);

    rope_rms_kernel<<<(M_ * H_) / 8, 256>>>(cosT, sinT, q, k);

    dim3 attn_grid(T_ / AQ, H_, B_);
    attn_mma_kernel<<<attn_grid, 256, SMEM_ATTN_BYTES>>>(q, k, v, o);

    dim3 gemm_grid(C_ / GBN, M_ / GBM);
    tf32_gemm_pipe<<<gemm_grid, GEMM_THREADS, GEMM_SMEM_BYTES>>>(o, wp, out);
}